// round 7
// baseline (speedup 1.0000x reference)
#include <cuda_runtime.h>

// Shapes (fixed by the problem)
#define B_  1024
#define Nn  64
#define F_  1024
#define H1_ 256
#define H2_ 128
#define NC_ 128
#define R_  65536          // B_*Nn
#define ALPHA_ 0.2f
#define BN_EPS_ 1e-5f

// -------- scratch (static __device__ arrays; no allocation) --------
__device__ float g_nbh1[R_ * H1_];     // 64 MB: layer-1 per-neighbor features
__device__ float g_x1[B_ * H1_];       // layer-1 output x (pre-BN)
__device__ float g_y[B_ * H1_];        // attention-weighted BN'd neighbors (layer 2)
__device__ float g_x2[B_ * H2_];       // layer-2 output x (pre-BN)
__device__ float g_t1[B_];             // self attention score part, layer 1
__device__ float g_wa11f[F_];          // W1^T @ a11
__device__ float g_wa21h[H1_];         // W2^T @ a21
__device__ float g_wa22h[H1_];         // W2^T @ a22
__device__ float g_bsum[B_];           // per-b sum of nbh1 (BN stats)
__device__ float g_bsumsq[B_];
__device__ float g_W2T[H1_ * H2_];     // W2 transposed [h1][h2]
__device__ float g_WlT[H2_ * NC_];     // Wl transposed [h2][c]
__device__ float g_scalars[8];         // 0:c11 1:c21 2:c22 3:xsum 4:xsq 5:x2sum 6:x2sq

__device__ __forceinline__ float sgnf(float v) {
    return (v > 0.f) ? 1.f : ((v < 0.f) ? -1.f : 0.f);
}

// block-wide sum with broadcast; sred must hold >= 9 floats
__device__ __forceinline__ float blockSumB(float v, float* sred) {
    const unsigned FULL = 0xffffffffu;
    #pragma unroll
    for (int o = 16; o; o >>= 1) v += __shfl_xor_sync(FULL, v, o);
    int lane = threadIdx.x & 31, wid = threadIdx.x >> 5;
    __syncthreads();                 // protect prior use of sred
    if (lane == 0) sred[wid] = v;
    __syncthreads();
    if (wid == 0) {
        float t = (lane * 32 < (int)blockDim.x) ? sred[lane] : 0.f;
        #pragma unroll
        for (int o = 4; o; o >>= 1) t += __shfl_xor_sync(FULL, t, o);
        if (lane == 0) sred[8] = t;
    }
    __syncthreads();
    return sred[8];
}

// -------- K0: precompute folded attention vectors, transposes, constants --------
__global__ void __launch_bounds__(256) k_pre(const float* __restrict__ W1,
                                             const float* __restrict__ b1,
                                             const float* __restrict__ a11,
                                             const float* __restrict__ W2,
                                             const float* __restrict__ b2,
                                             const float* __restrict__ a21,
                                             const float* __restrict__ a22,
                                             const float* __restrict__ Wl) {
    int t = blockIdx.x * 256 + threadIdx.x;   // 0..8191 (32 blocks)
    if (t < F_) {
        float s = 0.f;
        for (int h = 0; h < H1_; ++h) s += a11[h] * W1[h * F_ + t];
        g_wa11f[t] = s;
    }
    if (t < H1_) {
        float s21 = 0.f, s22 = 0.f;
        for (int h2 = 0; h2 < H2_; ++h2) {
            float w = W2[h2 * H1_ + t];
            s21 += a21[h2] * w;
            s22 += a22[h2] * w;
        }
        g_wa21h[t] = s21;
        g_wa22h[t] = s22;
    }
    // W2T[k*128 + h2] = W2[h2*256 + k]
    for (int i = t; i < H1_ * H2_; i += 8192) {
        int k = i / H2_, h2 = i % H2_;
        g_W2T[i] = W2[h2 * H1_ + k];
    }
    // WlT[h2*128 + c] = Wl[c*128 + h2]
    for (int i = t; i < H2_ * NC_; i += 8192) {
        int h2 = i / NC_, c = i % NC_;
        g_WlT[i] = Wl[c * H2_ + h2];
    }
    if (t == 0) {
        float c11 = 0.f;
        for (int h = 0; h < H1_; ++h) c11 += b1[h] * a11[h];
        float c21 = 0.f, c22 = 0.f;
        for (int h = 0; h < H2_; ++h) { c21 += b2[h] * a21[h]; c22 += b2[h] * a22[h]; }
        g_scalars[0] = c11;
        g_scalars[1] = c21;
        g_scalars[2] = c22;
        g_scalars[3] = 0.f; g_scalars[4] = 0.f;
        g_scalars[5] = 0.f; g_scalars[6] = 0.f;
    }
}

// -------- K1: t1[b] = sign(x[b,:]) . wa11f + c11 --------
__global__ void __launch_bounds__(256) k_t1(const float* __restrict__ x) {
    __shared__ float sred[16];
    int b = blockIdx.x;
    float s = 0.f;
    for (int f = threadIdx.x; f < F_; f += 256)
        s += sgnf(x[(size_t)b * F_ + f]) * g_wa11f[f];
    float tot = blockSumB(s, sred);
    if (threadIdx.x == 0) g_t1[b] = tot + g_scalars[0];
}

// -------- K2: the big GEMM: nbh1[r,h] = sum_f sign(nb[r,f]) * W1[h,f] + b1[h] --------
#define BM 128
#define BN 128
#define BK 16
#define TM 8
#define TN 8
__global__ void __launch_bounds__(256) k_gemm1(const float* __restrict__ A,
                                               const float* __restrict__ Bw,
                                               const float* __restrict__ bias) {
    __shared__ float As[BK][BM];
    __shared__ float Bs[BK][BN];
    const int tid  = threadIdx.x;
    const int cCol = blockIdx.x;        // 0..1
    const int cRow = blockIdx.y;        // 0..511
    const int tCol = tid & 15;
    const int tRow = tid >> 4;
    const int ldRow = tid >> 2;         // 0..63
    const int ldCol = (tid & 3) << 2;   // 0,4,8,12
    const float* Ab = A  + (size_t)cRow * BM * F_;
    const float* Bb = Bw + (size_t)cCol * BN * F_;

    float acc[TM][TN];
    #pragma unroll
    for (int i = 0; i < TM; ++i)
        #pragma unroll
        for (int j = 0; j < TN; ++j) acc[i][j] = 0.f;

    for (int k0 = 0; k0 < F_; k0 += BK) {
        #pragma unroll
        for (int p = 0; p < 2; ++p) {
            int r = ldRow + p * 64;
            float4 v = *reinterpret_cast<const float4*>(Ab + (size_t)r * F_ + k0 + ldCol);
            As[ldCol + 0][r] = sgnf(v.x);
            As[ldCol + 1][r] = sgnf(v.y);
            As[ldCol + 2][r] = sgnf(v.z);
            As[ldCol + 3][r] = sgnf(v.w);
            float4 w = *reinterpret_cast<const float4*>(Bb + (size_t)r * F_ + k0 + ldCol);
            Bs[ldCol + 0][r] = w.x;
            Bs[ldCol + 1][r] = w.y;
            Bs[ldCol + 2][r] = w.z;
            Bs[ldCol + 3][r] = w.w;
        }
        __syncthreads();
        #pragma unroll
        for (int kk = 0; kk < BK; ++kk) {
            float4 a0 = *reinterpret_cast<const float4*>(&As[kk][tRow * TM]);
            float4 a1 = *reinterpret_cast<const float4*>(&As[kk][tRow * TM + 4]);
            float4 b0 = *reinterpret_cast<const float4*>(&Bs[kk][tCol * TN]);
            float4 b1v = *reinterpret_cast<const float4*>(&Bs[kk][tCol * TN + 4]);
            float ra[8] = {a0.x, a0.y, a0.z, a0.w, a1.x, a1.y, a1.z, a1.w};
            float rb[8] = {b0.x, b0.y, b0.z, b0.w, b1v.x, b1v.y, b1v.z, b1v.w};
            #pragma unroll
            for (int i = 0; i < TM; ++i)
                #pragma unroll
                for (int j = 0; j < TN; ++j) acc[i][j] += ra[i] * rb[j];
        }
        __syncthreads();
    }

    const int hBase = cCol * BN + tCol * TN;
    float bj[TN];
    #pragma unroll
    for (int j = 0; j < TN; ++j) bj[j] = __ldg(&bias[hBase + j]);
    #pragma unroll
    for (int i = 0; i < TM; ++i) {
        size_t r = (size_t)cRow * BM + tRow * TM + i;
        float4 o0, o1;
        o0.x = acc[i][0] + bj[0]; o0.y = acc[i][1] + bj[1];
        o0.z = acc[i][2] + bj[2]; o0.w = acc[i][3] + bj[3];
        o1.x = acc[i][4] + bj[4]; o1.y = acc[i][5] + bj[5];
        o1.z = acc[i][6] + bj[6]; o1.w = acc[i][7] + bj[7];
        *reinterpret_cast<float4*>(&g_nbh1[r * H1_ + hBase])     = o0;
        *reinterpret_cast<float4*>(&g_nbh1[r * H1_ + hBase + 4]) = o1;
    }
}

// -------- K3: layer-1 attention + weighted sum + BN stats (one block per b) --------
__global__ void __launch_bounds__(256) k_attn1(const float* __restrict__ a12) {
    int b = blockIdx.x;
    int h = threadIdx.x;
    int lane = h & 31, warp = h >> 5;
    __shared__ float sa12[H1_];
    __shared__ float sS[Nn];
    __shared__ float sW[Nn];
    __shared__ float sred[16];
    sa12[h] = a12[h];
    __syncthreads();

    const float* base = g_nbh1 + (size_t)b * (Nn * H1_);
    float bsum = 0.f, bsq = 0.f;
    for (int ni = 0; ni < 8; ++ni) {
        int n = warp * 8 + ni;
        const float* row = base + n * H1_;
        float z = 0.f;
        #pragma unroll
        for (int j = 0; j < 8; ++j) {
            int hh = lane + 32 * j;
            float v = row[hh];
            bsum += v; bsq += v * v;
            z += v * sa12[hh];
        }
        #pragma unroll
        for (int o = 16; o; o >>= 1) z += __shfl_xor_sync(0xffffffffu, z, o);
        if (lane == 0) sS[n] = z;
    }
    __syncthreads();

    float t1 = g_t1[b];
    if (h < Nn) {
        float s = t1 + sS[h];
        sS[h] = (s > 0.f) ? s : ALPHA_ * s;
    }
    __syncthreads();
    float mx = -1e30f;
    for (int n = 0; n < Nn; ++n) mx = fmaxf(mx, sS[n]);
    float den = 0.f;
    for (int n = 0; n < Nn; ++n) den += expf(sS[n] - mx);
    if (h < Nn) sW[h] = expf(sS[h] - mx) / den;
    __syncthreads();

    float x1v = 0.f;
    #pragma unroll 8
    for (int n = 0; n < Nn; ++n) x1v += sW[n] * base[n * H1_ + h];
    g_x1[b * H1_ + h] = x1v;

    float tb = blockSumB(bsum, sred);
    if (h == 0) g_bsum[b] = tb;
    float tq = blockSumB(bsq, sred);
    if (h == 0) g_bsumsq[b] = tq;
    float xs = blockSumB(x1v, sred);
    if (h == 0) atomicAdd(&g_scalars[3], xs);
    float xq = blockSumB(x1v * x1v, sred);
    if (h == 0) atomicAdd(&g_scalars[4], xq);
}

// -------- K4: BN+ReLU + layer-2 attention; y[b,:] = sum_n A2 * relu(bn(nbh1)) --------
__global__ void __launch_bounds__(256) k_attn2(const float* __restrict__ g1p,
                                               const float* __restrict__ be1p) {
    int b = blockIdx.x;
    int h = threadIdx.x;
    int lane = h & 31, warp = h >> 5;
    __shared__ float swa[H1_];
    __shared__ float sS[Nn];
    __shared__ float sW[Nn];
    __shared__ float sred[16];
    swa[h] = g_wa22h[h];
    __syncthreads();

    float g1 = g1p[0], be1 = be1p[0];
    const float invb = 1.f / (float)(Nn * H1_);
    float mb = g_bsum[b] * invb;
    float vb = g_bsumsq[b] * invb - mb * mb;
    float ab = g1 * rsqrtf(vb + BN_EPS_);
    float bb = be1 - ab * mb;
    const float invx = 1.f / (float)(B_ * H1_);
    float mxm = g_scalars[3] * invx;
    float vx  = g_scalars[4] * invx - mxm * mxm;
    float ax  = g1 * rsqrtf(vx + BN_EPS_);
    float bx  = be1 - ax * mxm;

    // t2x = relu(bn(x1)) . wa21h + c21
    float u = fmaxf(ax * g_x1[b * H1_ + h] + bx, 0.f);
    float t2 = blockSumB(u * g_wa21h[h], sred) + g_scalars[1];

    const float* base = g_nbh1 + (size_t)b * (Nn * H1_);
    const float c22 = g_scalars[2];
    for (int ni = 0; ni < 8; ++ni) {
        int n = warp * 8 + ni;
        const float* row = base + n * H1_;
        float z = 0.f;
        #pragma unroll
        for (int j = 0; j < 8; ++j) {
            int hh = lane + 32 * j;
            float v = fmaxf(ab * row[hh] + bb, 0.f);
            z += v * swa[hh];
        }
        #pragma unroll
        for (int o = 16; o; o >>= 1) z += __shfl_xor_sync(0xffffffffu, z, o);
        if (lane == 0) sS[n] = z + c22;
    }
    __syncthreads();
    if (h < Nn) {
        float s = t2 + sS[h];
        sS[h] = (s > 0.f) ? s : ALPHA_ * s;
    }
    __syncthreads();
    float mx = -1e30f;
    for (int n = 0; n < Nn; ++n) mx = fmaxf(mx, sS[n]);
    float den = 0.f;
    for (int n = 0; n < Nn; ++n) den += expf(sS[n] - mx);
    if (h < Nn) sW[h] = expf(sS[h] - mx) / den;
    __syncthreads();

    float y = 0.f;
    #pragma unroll 8
    for (int n = 0; n < Nn; ++n) {
        float v = fmaxf(ab * base[n * H1_ + h] + bb, 0.f);
        y += sW[n] * v;
    }
    g_y[b * H1_ + h] = y;
}

// -------- K5: x2 = y @ W2^T + b2  (8 b-rows per block), accumulate BN stats --------
__global__ void __launch_bounds__(128) k_lin2(const float* __restrict__ b2) {
    int bb = blockIdx.x * 8;
    int h2 = threadIdx.x;
    __shared__ float sy[8 * H1_];
    __shared__ float sred[16];
    for (int i = h2; i < 8 * H1_; i += 128) sy[i] = g_y[(size_t)bb * H1_ + i];
    __syncthreads();
    float acc[8];
    #pragma unroll
    for (int i = 0; i < 8; ++i) acc[i] = 0.f;
    for (int k = 0; k < H1_; ++k) {
        float w = g_W2T[k * H2_ + h2];
        #pragma unroll
        for (int i = 0; i < 8; ++i) acc[i] += sy[i * H1_ + k] * w;
    }
    float b2v = b2[h2];
    float ls = 0.f, lq = 0.f;
    #pragma unroll
    for (int i = 0; i < 8; ++i) {
        float s = acc[i] + b2v;
        g_x2[(size_t)(bb + i) * H2_ + h2] = s;
        ls += s; lq += s * s;
    }
    float a = blockSumB(ls, sred);
    if (h2 == 0) atomicAdd(&g_scalars[5], a);
    float q = blockSumB(lq, sred);
    if (h2 == 0) atomicAdd(&g_scalars[6], q);
}

// -------- K6: logits = relu(bn(x2)) @ Wl^T + bl  (8 b-rows per block) --------
__global__ void __launch_bounds__(128) k_final(const float* __restrict__ g2p,
                                               const float* __restrict__ be2p,
                                               const float* __restrict__ bl,
                                               float* __restrict__ out) {
    int bb = blockIdx.x * 8;
    int c = threadIdx.x;
    const float inv2 = 1.f / (float)(B_ * H2_);
    float m = g_scalars[5] * inv2;
    float v = g_scalars[6] * inv2 - m * m;
    float a2 = g2p[0] * rsqrtf(v + BN_EPS_);
    float s2 = be2p[0] - a2 * m;
    __shared__ float sx[8 * H2_];
    #pragma unroll
    for (int i = 0; i < 8; ++i) {
        float t = a2 * g_x2[(size_t)(bb + i) * H2_ + c] + s2;
        sx[i * H2_ + c] = fmaxf(t, 0.f);
    }
    __syncthreads();
    float acc[8];
    #pragma unroll
    for (int i = 0; i < 8; ++i) acc[i] = 0.f;
    for (int k = 0; k < H2_; ++k) {
        float w = g_WlT[k * NC_ + c];
        #pragma unroll
        for (int i = 0; i < 8; ++i) acc[i] += sx[i * H2_ + k] * w;
    }
    float blc = bl[c];
    #pragma unroll
    for (int i = 0; i < 8; ++i) out[(size_t)(bb + i) * NC_ + c] = acc[i] + blc;
}

extern "C" void kernel_launch(void* const* d_in, const int* in_sizes, int n_in,
                              void* d_out, int out_size) {
    const float* x   = (const float*)d_in[0];
    const float* nb  = (const float*)d_in[1];
    const float* W1  = (const float*)d_in[2];
    const float* b1  = (const float*)d_in[3];
    const float* a11 = (const float*)d_in[4];
    const float* a12 = (const float*)d_in[5];
    const float* g1  = (const float*)d_in[6];
    const float* be1 = (const float*)d_in[7];
    const float* W2  = (const float*)d_in[8];
    const float* b2  = (const float*)d_in[9];
    const float* a21 = (const float*)d_in[10];
    const float* a22 = (const float*)d_in[11];
    const float* g2  = (const float*)d_in[12];
    const float* be2 = (const float*)d_in[13];
    const float* Wl  = (const float*)d_in[14];
    const float* bl  = (const float*)d_in[15];
    float* out = (float*)d_out;

    k_pre<<<32, 256>>>(W1, b1, a11, W2, b2, a21, a22, Wl);
    k_t1<<<B_, 256>>>(x);
    dim3 gg(2, 512);
    k_gemm1<<<gg, 256>>>(nb, W1, b1);
    k_attn1<<<B_, 256>>>(a12);
    k_attn2<<<B_, 256>>>(g1, be1);
    k_lin2<<<B_ / 8, 128>>>(b2);
    k_final<<<B_ / 8, 128>>>(g2, be2, bl, out);
}

// round 10
// speedup vs baseline: 2.4185x; 2.4185x over previous
#include <cuda_runtime.h>
#include <cuda_bf16.h>
#include <cstdint>

// Shapes (fixed by the problem)
#define B_  1024
#define Nn  64
#define F_  1024
#define H1_ 256
#define H2_ 128
#define NC_ 128
#define R_  65536          // B_*Nn
#define ALPHA_ 0.2f
#define BN_EPS_ 1e-5f

// -------- scratch (static __device__ arrays; no allocation) --------
__device__ float g_nbh1[R_ * H1_];     // 64 MB: layer-1 per-neighbor features
__device__ float g_x1[B_ * H1_];       // layer-1 output x (pre-BN)
__device__ float g_y[B_ * H1_];        // attention-weighted BN'd neighbors (layer 2)
__device__ float g_x2[B_ * H2_];       // layer-2 output x (pre-BN)
__device__ float g_t1[B_];             // self attention score part, layer 1
__device__ float g_wa11f[F_];          // W1^T @ a11
__device__ float g_wa21h[H1_];         // W2^T @ a21
__device__ float g_wa22h[H1_];         // W2^T @ a22
__device__ float g_bsum[B_];           // per-b sum of nbh1 (BN stats)
__device__ float g_bsumsq[B_];
__device__ float g_W2T[H1_ * H2_];     // W2 transposed [h1][h2]
__device__ float g_WlT[H2_ * NC_];     // Wl transposed [h2][c]
__device__ float g_scalars[8];         // 0:c11 1:c21 2:c22 3:xsum 4:xsq 5:x2sum 6:x2sq
__device__ __nv_bfloat16 g_W1hi[H1_ * F_];   // bf16 split of W1
__device__ __nv_bfloat16 g_W1lo[H1_ * F_];

__device__ __forceinline__ float sgnf(float v) {
    return (v > 0.f) ? 1.f : ((v < 0.f) ? -1.f : 0.f);
}
__device__ __forceinline__ uint32_t sgnbf(float v) {
    return (v > 0.f) ? 0x3F80u : ((v < 0.f) ? 0xBF80u : 0u);
}
__device__ __forceinline__ uint32_t pack2(float x, float y) {
    return sgnbf(x) | (sgnbf(y) << 16);
}

// block-wide sum with broadcast; sred must hold >= 9 floats
__device__ __forceinline__ float blockSumB(float v, float* sred) {
    const unsigned FULL = 0xffffffffu;
    #pragma unroll
    for (int o = 16; o; o >>= 1) v += __shfl_xor_sync(FULL, v, o);
    int lane = threadIdx.x & 31, wid = threadIdx.x >> 5;
    __syncthreads();
    if (lane == 0) sred[wid] = v;
    __syncthreads();
    if (wid == 0) {
        float t = (lane * 32 < (int)blockDim.x) ? sred[lane] : 0.f;
        #pragma unroll
        for (int o = 4; o; o >>= 1) t += __shfl_xor_sync(FULL, t, o);
        if (lane == 0) sred[8] = t;
    }
    __syncthreads();
    return sred[8];
}

// ================= mma.sync helpers (portable sm_80+ HMMA path) =================
__device__ __forceinline__ uint32_t smem_u32(const void* p) {
    uint32_t a;
    asm("{ .reg .u64 t; cvta.to.shared.u64 t, %1; cvt.u32.u64 %0, t; }" : "=r"(a) : "l"(p));
    return a;
}
__device__ __forceinline__ void ldsm4(uint32_t* r, uint32_t addr) {
    asm volatile("ldmatrix.sync.aligned.m8n8.x4.shared.b16 {%0,%1,%2,%3}, [%4];"
                 : "=r"(r[0]), "=r"(r[1]), "=r"(r[2]), "=r"(r[3]) : "r"(addr));
}
__device__ __forceinline__ void mma_bf16(float* d, const uint32_t* a, const uint32_t* b) {
    asm volatile(
        "mma.sync.aligned.m16n8k16.row.col.f32.bf16.bf16.f32 "
        "{%0,%1,%2,%3}, {%4,%5,%6,%7}, {%8,%9}, {%0,%1,%2,%3};"
        : "+f"(d[0]), "+f"(d[1]), "+f"(d[2]), "+f"(d[3])
        : "r"(a[0]), "r"(a[1]), "r"(a[2]), "r"(a[3]), "r"(b[0]), "r"(b[1]));
}
#define SWZ(o) ((o) ^ (((o) >> 3) & 0x70))

// -------- K0: precompute folded vectors, W1 bf16 split, transposes, constants --------
__global__ void __launch_bounds__(256) k_pre(const float* __restrict__ W1,
                                             const float* __restrict__ b1,
                                             const float* __restrict__ a11,
                                             const float* __restrict__ W2,
                                             const float* __restrict__ b2,
                                             const float* __restrict__ a21,
                                             const float* __restrict__ a22,
                                             const float* __restrict__ Wl) {
    int t = blockIdx.x * 256 + threadIdx.x;   // 0..8191 (32 blocks)
    if (t < F_) {
        float s = 0.f;
        for (int h = 0; h < H1_; ++h) s += a11[h] * W1[h * F_ + t];
        g_wa11f[t] = s;
    }
    if (t < H1_) {
        float s21 = 0.f, s22 = 0.f;
        for (int h2 = 0; h2 < H2_; ++h2) {
            float w = W2[h2 * H1_ + t];
            s21 += a21[h2] * w;
            s22 += a22[h2] * w;
        }
        g_wa21h[t] = s21;
        g_wa22h[t] = s22;
    }
    // bf16 split of W1
    for (int i = t; i < H1_ * F_; i += 8192) {
        float w = W1[i];
        __nv_bfloat16 hi = __float2bfloat16(w);
        g_W1hi[i] = hi;
        g_W1lo[i] = __float2bfloat16(w - __bfloat162float(hi));
    }
    for (int i = t; i < H1_ * H2_; i += 8192) {
        int k = i / H2_, h2 = i % H2_;
        g_W2T[i] = W2[h2 * H1_ + k];
    }
    for (int i = t; i < H2_ * NC_; i += 8192) {
        int h2 = i / NC_, c = i % NC_;
        g_WlT[i] = Wl[c * H2_ + h2];
    }
    if (t == 0) {
        float c11 = 0.f;
        for (int h = 0; h < H1_; ++h) c11 += b1[h] * a11[h];
        float c21 = 0.f, c22 = 0.f;
        for (int h = 0; h < H2_; ++h) { c21 += b2[h] * a21[h]; c22 += b2[h] * a22[h]; }
        g_scalars[0] = c11; g_scalars[1] = c21; g_scalars[2] = c22;
        g_scalars[3] = 0.f; g_scalars[4] = 0.f; g_scalars[5] = 0.f; g_scalars[6] = 0.f;
    }
}

// -------- K1: t1[b] = sign(x[b,:]) . wa11f + c11 --------
__global__ void __launch_bounds__(256) k_t1(const float* __restrict__ x) {
    __shared__ float sred[16];
    int b = blockIdx.x;
    float s = 0.f;
    for (int f = threadIdx.x; f < F_; f += 256)
        s += sgnf(x[(size_t)b * F_ + f]) * g_wa11f[f];
    float tot = blockSumB(s, sred);
    if (threadIdx.x == 0) g_t1[b] = tot + g_scalars[0];
}

// -------- K2: HMMA GEMM (nbh1 = sign(nb)@W1^T + b1) fused with attn1 --------
// 1024 CTAs, one batch element each: M=64 rows (neighbors), N=256 (H1), K=1024 x {hi,lo}
#define SM_A    0          // 64 x 128B      = 8192
#define SM_BH   8192       // 256 x 128B     = 32768
#define SM_BL   40960      // 256 x 128B     = 32768  (GEMM region ends at 73728)
#define SM_B1   73728      // 256 floats
#define SM_A12  74752      // 256 floats
#define SM_SZ   75776      // 64 floats
#define SM_SRS  76032      // 64 floats
#define SM_SRQ  76288      // 64 floats
#define SM_SW   76544      // 64 floats
#define SM_RED  76800      // 16 floats
#define GEMM_SMEM 76864
#define SD_LD   260        // padded sD row stride (floats): conflict-free row access

__global__ void __launch_bounds__(256, 2) k_gemm(const float* __restrict__ nb,
                                                 const float* __restrict__ b1,
                                                 const float* __restrict__ a12) {
    extern __shared__ char dsm[];
    const int tid = threadIdx.x;
    const int lane = tid & 31, wid = tid >> 5;
    const int wm = wid >> 2;          // 0..1  (32-row slab)
    const int wn = wid & 3;           // 0..3  (64-col slab)
    const int b = blockIdx.x;

    const uint32_t sbase = smem_u32(dsm);
    const uint32_t aS  = sbase + SM_A;
    const uint32_t bhS = sbase + SM_BH;
    const uint32_t blS = sbase + SM_BL;

    // stage b1 / a12 into smem (region untouched by GEMM buffers)
    ((float*)(dsm + SM_B1))[tid]  = b1[tid];
    ((float*)(dsm + SM_A12))[tid] = a12[tid];

    // ---- per-thread ldmatrix address bases (pre-swizzled; XOR kb later) ----
    uint32_t a_base[2];
    #pragma unroll
    for (int mt = 0; mt < 2; ++mt) {
        uint32_t off = (uint32_t)(((wm << 5) + (mt << 4) + (lane & 15)) * 128 + (lane & 16));
        a_base[mt] = SWZ(off);
    }
    uint32_t b_base[4];
    {
        int nr = (wn << 6) + (lane & 7) + ((lane & 16) >> 1);
        uint32_t off = (uint32_t)(nr * 128 + ((lane & 8) << 1));
        uint32_t s0 = SWZ(off);
        #pragma unroll
        for (int g = 0; g < 4; ++g) b_base[g] = s0 + ((uint32_t)g << 11);
    }

    float acc[2][8][4];
    #pragma unroll
    for (int mt = 0; mt < 2; ++mt)
        #pragma unroll
        for (int nt = 0; nt < 8; ++nt)
            #pragma unroll
            for (int e = 0; e < 4; ++e) acc[mt][nt][e] = 0.f;

    const float* Ab = nb + (size_t)b * 64 * F_;
    const int arow = tid >> 2;
    const int acs  = (tid & 3) << 4;      // col seg: 0,16,32,48

    #pragma unroll 1
    for (int c = 0; c < 16; ++c) {
        if (c) __syncthreads();
        const int k0 = c * 64;
        // A: 64x64 fp32 -> sign bf16, SW128-swizzled
        {
            const float* ap = Ab + (size_t)arow * F_ + k0 + acs;
            float4 v0 = *reinterpret_cast<const float4*>(ap);
            float4 v1 = *reinterpret_cast<const float4*>(ap + 4);
            float4 v2 = *reinterpret_cast<const float4*>(ap + 8);
            float4 v3 = *reinterpret_cast<const float4*>(ap + 12);
            uint32_t base = (uint32_t)(arow * 128 + (acs << 1));
            *reinterpret_cast<uint4*>(dsm + SM_A + SWZ(base)) =
                make_uint4(pack2(v0.x, v0.y), pack2(v0.z, v0.w),
                           pack2(v1.x, v1.y), pack2(v1.z, v1.w));
            *reinterpret_cast<uint4*>(dsm + SM_A + SWZ(base + 16)) =
                make_uint4(pack2(v2.x, v2.y), pack2(v2.z, v2.w),
                           pack2(v3.x, v3.y), pack2(v3.z, v3.w));
        }
        // B hi/lo: 256x64 bf16 each, swizzled
        #pragma unroll
        for (int i = 0; i < 8; ++i) {
            int idx = tid + (i << 8);
            int row = idx >> 3, seg = idx & 7;
            uint32_t sw = SWZ((uint32_t)(row * 128 + seg * 16));
            const size_t gidx = (size_t)row * F_ + k0 + seg * 8;
            *reinterpret_cast<uint4*>(dsm + SM_BH + sw) =
                *reinterpret_cast<const uint4*>(g_W1hi + gidx);
            *reinterpret_cast<uint4*>(dsm + SM_BL + sw) =
                *reinterpret_cast<const uint4*>(g_W1lo + gidx);
        }
        __syncthreads();

        #pragma unroll
        for (int ks = 0; ks < 4; ++ks) {
            const uint32_t kb = (uint32_t)ks << 5;
            uint32_t ra[2][4];
            ldsm4(ra[0], aS + (a_base[0] ^ kb));
            ldsm4(ra[1], aS + (a_base[1] ^ kb));
            uint32_t rb[8][2];
            #pragma unroll
            for (int g = 0; g < 4; ++g) {
                uint32_t t4[4];
                ldsm4(t4, bhS + (b_base[g] ^ kb));
                rb[2*g][0] = t4[0]; rb[2*g][1] = t4[1];
                rb[2*g+1][0] = t4[2]; rb[2*g+1][1] = t4[3];
            }
            #pragma unroll
            for (int mt = 0; mt < 2; ++mt)
                #pragma unroll
                for (int nt = 0; nt < 8; ++nt)
                    mma_bf16(acc[mt][nt], ra[mt], rb[nt]);
            #pragma unroll
            for (int g = 0; g < 4; ++g) {
                uint32_t t4[4];
                ldsm4(t4, blS + (b_base[g] ^ kb));
                rb[2*g][0] = t4[0]; rb[2*g][1] = t4[1];
                rb[2*g+1][0] = t4[2]; rb[2*g+1][1] = t4[3];
            }
            #pragma unroll
            for (int mt = 0; mt < 2; ++mt)
                #pragma unroll
                for (int nt = 0; nt < 8; ++nt)
                    mma_bf16(acc[mt][nt], ra[mt], rb[nt]);
        }
    }
    __syncthreads();   // all warps done reading GEMM buffers

    // ---------------- fused attn1 epilogue ----------------
    float* sD = (float*)dsm;                       // [64][SD_LD], aliases GEMM bufs
    const float* b1s  = (const float*)(dsm + SM_B1);
    const float* a12s = (const float*)(dsm + SM_A12);
    float* sz  = (float*)(dsm + SM_SZ);
    float* srs = (float*)(dsm + SM_SRS);
    float* srq = (float*)(dsm + SM_SRQ);
    float* sW  = (float*)(dsm + SM_SW);
    float* sred = (float*)(dsm + SM_RED);

    {
        const int g8 = lane >> 2, tq = lane & 3;
        #pragma unroll
        for (int mt = 0; mt < 2; ++mt) {
            int row = (wm << 5) + (mt << 4) + g8;
            #pragma unroll
            for (int nt = 0; nt < 8; ++nt) {
                int col = (wn << 6) + (nt << 3) + (tq << 1);
                sD[row * SD_LD + col]           = acc[mt][nt][0] + b1s[col];
                sD[row * SD_LD + col + 1]       = acc[mt][nt][1] + b1s[col + 1];
                sD[(row + 8) * SD_LD + col]     = acc[mt][nt][2] + b1s[col];
                sD[(row + 8) * SD_LD + col + 1] = acc[mt][nt][3] + b1s[col + 1];
            }
        }
    }
    __syncthreads();

    // row stats: 4 threads per row, stride-4 columns
    {
        const int r = tid >> 2, ph = tid & 3;
        float rs = 0.f, rq = 0.f, zz = 0.f;
        #pragma unroll 8
        for (int j = 0; j < 64; ++j) {
            int cc = ph + 4 * j;
            float v = sD[r * SD_LD + cc];
            rs += v; rq += v * v; zz += v * a12s[cc];
        }
        rs += __shfl_xor_sync(0xffffffffu, rs, 1); rs += __shfl_xor_sync(0xffffffffu, rs, 2);
        rq += __shfl_xor_sync(0xffffffffu, rq, 1); rq += __shfl_xor_sync(0xffffffffu, rq, 2);
        zz += __shfl_xor_sync(0xffffffffu, zz, 1); zz += __shfl_xor_sync(0xffffffffu, zz, 2);
        if (ph == 0) {
            srs[r] = rs; srq[r] = rq;
            float l = zz + g_t1[b];
            sz[r] = (l > 0.f) ? l : ALPHA_ * l;
        }
    }
    __syncthreads();

    if (tid < 64) {
        float mx = -1e30f;
        for (int j = 0; j < 64; ++j) mx = fmaxf(mx, sz[j]);
        float den = 0.f;
        for (int j = 0; j < 64; ++j) den += expf(sz[j] - mx);
        sW[tid] = expf(sz[tid] - mx) / den;
    }
    if (tid == 0) {
        float s = 0.f, q = 0.f;
        for (int j = 0; j < 64; ++j) { s += srs[j]; q += srq[j]; }
        g_bsum[b] = s; g_bsumsq[b] = q;
    }
    __syncthreads();

    // x1[h] = sum_n sW[n]*D[n][h]; also write nbh1 to global
    {
        float accx = 0.f;
        float* gout = g_nbh1 + (size_t)b * (Nn * H1_);
        #pragma unroll 8
        for (int n = 0; n < Nn; ++n) {
            float v = sD[n * SD_LD + tid];
            gout[n * H1_ + tid] = v;
            accx += sW[n] * v;
        }
        g_x1[(size_t)b * H1_ + tid] = accx;
        float ts = blockSumB(accx, sred);
        if (tid == 0) atomicAdd(&g_scalars[3], ts);
        float tq2 = blockSumB(accx * accx, sred);
        if (tid == 0) atomicAdd(&g_scalars[4], tq2);
    }
}

// -------- K4: BN+ReLU + layer-2 attention; y[b,:] = sum_n A2 * relu(bn(nbh1)) --------
__global__ void __launch_bounds__(256) k_attn2(const float* __restrict__ g1p,
                                               const float* __restrict__ be1p) {
    int b = blockIdx.x;
    int h = threadIdx.x;
    int lane = h & 31, warp = h >> 5;
    __shared__ float swa[H1_];
    __shared__ float sS[Nn];
    __shared__ float sW[Nn];
    __shared__ float sred[16];
    swa[h] = g_wa22h[h];
    __syncthreads();

    float g1 = g1p[0], be1 = be1p[0];
    const float invb = 1.f / (float)(Nn * H1_);
    float mb = g_bsum[b] * invb;
    float vb = g_bsumsq[b] * invb - mb * mb;
    float ab = g1 * rsqrtf(vb + BN_EPS_);
    float bb = be1 - ab * mb;
    const float invx = 1.f / (float)(B_ * H1_);
    float mxm = g_scalars[3] * invx;
    float vx  = g_scalars[4] * invx - mxm * mxm;
    float ax  = g1 * rsqrtf(vx + BN_EPS_);
    float bx  = be1 - ax * mxm;

    float u = fmaxf(ax * g_x1[b * H1_ + h] + bx, 0.f);
    float t2 = blockSumB(u * g_wa21h[h], sred) + g_scalars[1];

    const float* base = g_nbh1 + (size_t)b * (Nn * H1_);
    const float c22 = g_scalars[2];
    for (int ni = 0; ni < 8; ++ni) {
        int n = warp * 8 + ni;
        const float* row = base + n * H1_;
        float z = 0.f;
        #pragma unroll
        for (int j = 0; j < 8; ++j) {
            int hh = lane + 32 * j;
            float v = fmaxf(ab * row[hh] + bb, 0.f);
            z += v * swa[hh];
        }
        #pragma unroll
        for (int o = 16; o; o >>= 1) z += __shfl_xor_sync(0xffffffffu, z, o);
        if (lane == 0) sS[n] = z + c22;
    }
    __syncthreads();
    if (h < Nn) {
        float s = t2 + sS[h];
        sS[h] = (s > 0.f) ? s : ALPHA_ * s;
    }
    __syncthreads();
    float mx = -1e30f;
    for (int n = 0; n < Nn; ++n) mx = fmaxf(mx, sS[n]);
    float den = 0.f;
    for (int n = 0; n < Nn; ++n) den += expf(sS[n] - mx);
    if (h < Nn) sW[h] = expf(sS[h] - mx) / den;
    __syncthreads();

    float y = 0.f;
    #pragma unroll 8
    for (int n = 0; n < Nn; ++n) {
        float v = fmaxf(ab * base[n * H1_ + h] + bb, 0.f);
        y += sW[n] * v;
    }
    g_y[b * H1_ + h] = y;
}

// -------- K5: x2 = y @ W2^T + b2 --------
__global__ void __launch_bounds__(128) k_lin2(const float* __restrict__ b2) {
    int bb = blockIdx.x * 8;
    int h2 = threadIdx.x;
    __shared__ float sy[8 * H1_];
    __shared__ float sred[16];
    for (int i = h2; i < 8 * H1_; i += 128) sy[i] = g_y[(size_t)bb * H1_ + i];
    __syncthreads();
    float acc[8];
    #pragma unroll
    for (int i = 0; i < 8; ++i) acc[i] = 0.f;
    for (int k = 0; k < H1_; ++k) {
        float w = g_W2T[k * H2_ + h2];
        #pragma unroll
        for (int i = 0; i < 8; ++i) acc[i] += sy[i * H1_ + k] * w;
    }
    float b2v = b2[h2];
    float ls = 0.f, lq = 0.f;
    #pragma unroll
    for (int i = 0; i < 8; ++i) {
        float s = acc[i] + b2v;
        g_x2[(size_t)(bb + i) * H2_ + h2] = s;
        ls += s; lq += s * s;
    }
    float a = blockSumB(ls, sred);
    if (h2 == 0) atomicAdd(&g_scalars[5], a);
    float q = blockSumB(lq, sred);
    if (h2 == 0) atomicAdd(&g_scalars[6], q);
}

// -------- K6: logits = relu(bn(x2)) @ Wl^T + bl --------
__global__ void __launch_bounds__(128) k_final(const float* __restrict__ g2p,
                                               const float* __restrict__ be2p,
                                               const float* __restrict__ bl,
                                               float* __restrict__ out) {
    int bb = blockIdx.x * 8;
    int c = threadIdx.x;
    const float inv2 = 1.f / (float)(B_ * H2_);
    float m = g_scalars[5] * inv2;
    float v = g_scalars[6] * inv2 - m * m;
    float a2 = g2p[0] * rsqrtf(v + BN_EPS_);
    float s2 = be2p[0] - a2 * m;
    __shared__ float sx[8 * H2_];
    #pragma unroll
    for (int i = 0; i < 8; ++i) {
        float t = a2 * g_x2[(size_t)(bb + i) * H2_ + c] + s2;
        sx[i * H2_ + c] = fmaxf(t, 0.f);
    }
    __syncthreads();
    float acc[8];
    #pragma unroll
    for (int i = 0; i < 8; ++i) acc[i] = 0.f;
    for (int k = 0; k < H2_; ++k) {
        float w = g_WlT[k * NC_ + c];
        #pragma unroll
        for (int i = 0; i < 8; ++i) acc[i] += sx[i * H2_ + k] * w;
    }
    float blc = bl[c];
    #pragma unroll
    for (int i = 0; i < 8; ++i) out[(size_t)(bb + i) * NC_ + c] = acc[i] + blc;
}

extern "C" void kernel_launch(void* const* d_in, const int* in_sizes, int n_in,
                              void* d_out, int out_size) {
    const float* x   = (const float*)d_in[0];
    const float* nb  = (const float*)d_in[1];
    const float* W1  = (const float*)d_in[2];
    const float* b1  = (const float*)d_in[3];
    const float* a11 = (const float*)d_in[4];
    const float* a12 = (const float*)d_in[5];
    const float* g1  = (const float*)d_in[6];
    const float* be1 = (const float*)d_in[7];
    const float* W2  = (const float*)d_in[8];
    const float* b2  = (const float*)d_in[9];
    const float* a21 = (const float*)d_in[10];
    const float* a22 = (const float*)d_in[11];
    const float* g2  = (const float*)d_in[12];
    const float* be2 = (const float*)d_in[13];
    const float* Wl  = (const float*)d_in[14];
    const float* bl  = (const float*)d_in[15];
    float* out = (float*)d_out;

    static int smem_set = 0;
    if (!smem_set) {
        cudaFuncSetAttribute(k_gemm, cudaFuncAttributeMaxDynamicSharedMemorySize, GEMM_SMEM);
        smem_set = 1;
    }

    k_pre<<<32, 256>>>(W1, b1, a11, W2, b2, a21, a22, Wl);
    k_t1<<<B_, 256>>>(x);
    k_gemm<<<B_, 256, GEMM_SMEM>>>(nb, b1, a12);
    k_attn2<<<B_, 256>>>(g1, be1);
    k_lin2<<<B_ / 8, 128>>>(b2);
    k_final<<<B_ / 8, 128>>>(g2, be2, bl, out);
}

// round 13
// speedup vs baseline: 2.7302x; 1.1289x over previous
#include <cuda_runtime.h>
#include <cuda_bf16.h>
#include <cstdint>

// Shapes (fixed by the problem)
#define B_  1024
#define Nn  64
#define F_  1024
#define H1_ 256
#define H2_ 128
#define NC_ 128
#define R_  65536          // B_*Nn
#define ALPHA_ 0.2f
#define BN_EPS_ 1e-5f

// -------- scratch (static __device__ arrays; no allocation) --------
__device__ float g_nbh1[R_ * H1_];     // 64 MB: layer-1 per-neighbor features
__device__ float g_x1[B_ * H1_];       // layer-1 output x (pre-BN)
__device__ float g_y[B_ * H1_];        // attention-weighted BN'd neighbors (layer 2)
__device__ float g_x2[B_ * H2_];       // layer-2 output x (pre-BN)
__device__ float g_t1[B_];             // self attention score part, layer 1
__device__ float g_wa11f[F_];          // W1^T @ a11
__device__ float g_wa21h[H1_];         // W2^T @ a21
__device__ float g_wa22h[H1_];         // W2^T @ a22
__device__ float g_bsum[B_];           // per-b sum of nbh1 (BN stats)
__device__ float g_bsumsq[B_];
__device__ float g_W2T[H1_ * H2_];     // W2 transposed [h1][h2]
__device__ float g_WlT[H2_ * NC_];     // Wl transposed [h2][c]
__device__ float g_scalars[8];         // 0:c11 1:c21 2:c22 3:xsum 4:xsq 5:x2sum 6:x2sq
__device__ __nv_bfloat16 g_W1hi[H1_ * F_];   // bf16 split of W1
__device__ __nv_bfloat16 g_W1lo[H1_ * F_];

__device__ __forceinline__ float sgnf(float v) {
    return (v > 0.f) ? 1.f : ((v < 0.f) ? -1.f : 0.f);
}
__device__ __forceinline__ uint32_t sgnbf(float v) {
    return (v > 0.f) ? 0x3F80u : ((v < 0.f) ? 0xBF80u : 0u);
}
__device__ __forceinline__ uint32_t pack2(float x, float y) {
    return sgnbf(x) | (sgnbf(y) << 16);
}

// block-wide sum with broadcast; sred must hold >= 32 floats; result in sred[16]
__device__ __forceinline__ float blockSumB(float v, float* sred) {
    const unsigned FULL = 0xffffffffu;
    #pragma unroll
    for (int o = 16; o; o >>= 1) v += __shfl_xor_sync(FULL, v, o);
    int lane = threadIdx.x & 31, wid = threadIdx.x >> 5;
    __syncthreads();
    if (lane == 0) sred[wid] = v;
    __syncthreads();
    if (wid == 0) {
        float t = (lane * 32 < (int)blockDim.x) ? sred[lane] : 0.f;
        #pragma unroll
        for (int o = 16; o; o >>= 1) t += __shfl_xor_sync(FULL, t, o);
        if (lane == 0) sred[16] = t;
    }
    __syncthreads();
    return sred[16];
}

// ================= mma.sync helpers (portable sm_80+ HMMA path) =================
__device__ __forceinline__ uint32_t smem_u32(const void* p) {
    uint32_t a;
    asm("{ .reg .u64 t; cvta.to.shared.u64 t, %1; cvt.u32.u64 %0, t; }" : "=r"(a) : "l"(p));
    return a;
}
__device__ __forceinline__ void ldsm4(uint32_t* r, uint32_t addr) {
    asm volatile("ldmatrix.sync.aligned.m8n8.x4.shared.b16 {%0,%1,%2,%3}, [%4];"
                 : "=r"(r[0]), "=r"(r[1]), "=r"(r[2]), "=r"(r[3]) : "r"(addr));
}
__device__ __forceinline__ void mma_bf16(float* d, const uint32_t* a, const uint32_t* b) {
    asm volatile(
        "mma.sync.aligned.m16n8k16.row.col.f32.bf16.bf16.f32 "
        "{%0,%1,%2,%3}, {%4,%5,%6,%7}, {%8,%9}, {%0,%1,%2,%3};"
        : "+f"(d[0]), "+f"(d[1]), "+f"(d[2]), "+f"(d[3])
        : "r"(a[0]), "r"(a[1]), "r"(a[2]), "r"(a[3]), "r"(b[0]), "r"(b[1]));
}
__device__ __forceinline__ void cp_async16(uint32_t dst, const void* src) {
    asm volatile("cp.async.cg.shared.global [%0], [%1], 16;" :: "r"(dst), "l"(src));
}
#define CP_COMMIT() asm volatile("cp.async.commit_group;" ::: "memory")
#define CP_WAIT1()  asm volatile("cp.async.wait_group 1;" ::: "memory")
#define CP_WAIT0()  asm volatile("cp.async.wait_group 0;" ::: "memory")
#define SWZ(o) ((o) ^ (((o) >> 3) & 0x70))

// -------- K0: precompute folded vectors, W1 bf16 split, transposes, constants --------
__global__ void __launch_bounds__(256) k_pre(const float* __restrict__ W1,
                                             const float* __restrict__ b1,
                                             const float* __restrict__ a11,
                                             const float* __restrict__ W2,
                                             const float* __restrict__ b2,
                                             const float* __restrict__ a21,
                                             const float* __restrict__ a22,
                                             const float* __restrict__ Wl) {
    int t = blockIdx.x * 256 + threadIdx.x;   // 0..8191 (32 blocks)
    if (t < F_) {
        float s = 0.f;
        for (int h = 0; h < H1_; ++h) s += a11[h] * W1[h * F_ + t];
        g_wa11f[t] = s;
    }
    if (t < H1_) {
        float s21 = 0.f, s22 = 0.f;
        for (int h2 = 0; h2 < H2_; ++h2) {
            float w = W2[h2 * H1_ + t];
            s21 += a21[h2] * w;
            s22 += a22[h2] * w;
        }
        g_wa21h[t] = s21;
        g_wa22h[t] = s22;
    }
    // bf16 split of W1
    for (int i = t; i < H1_ * F_; i += 8192) {
        float w = W1[i];
        __nv_bfloat16 hi = __float2bfloat16(w);
        g_W1hi[i] = hi;
        g_W1lo[i] = __float2bfloat16(w - __bfloat162float(hi));
    }
    for (int i = t; i < H1_ * H2_; i += 8192) {
        int k = i / H2_, h2 = i % H2_;
        g_W2T[i] = W2[h2 * H1_ + k];
    }
    for (int i = t; i < H2_ * NC_; i += 8192) {
        int h2 = i / NC_, c = i % NC_;
        g_WlT[i] = Wl[c * H2_ + h2];
    }
    if (t == 0) {
        float c11 = 0.f;
        for (int h = 0; h < H1_; ++h) c11 += b1[h] * a11[h];
        float c21 = 0.f, c22 = 0.f;
        for (int h = 0; h < H2_; ++h) { c21 += b2[h] * a21[h]; c22 += b2[h] * a22[h]; }
        g_scalars[0] = c11; g_scalars[1] = c21; g_scalars[2] = c22;
        g_scalars[3] = 0.f; g_scalars[4] = 0.f; g_scalars[5] = 0.f; g_scalars[6] = 0.f;
    }
}

// -------- K1: t1[b] = sign(x[b,:]) . wa11f + c11 --------
__global__ void __launch_bounds__(256) k_t1(const float* __restrict__ x) {
    __shared__ float sred[32];
    int b = blockIdx.x;
    float s = 0.f;
    for (int f = threadIdx.x; f < F_; f += 256)
        s += sgnf(x[(size_t)b * F_ + f]) * g_wa11f[f];
    float tot = blockSumB(s, sred);
    if (threadIdx.x == 0) g_t1[b] = tot + g_scalars[0];
}

// -------- K2: pipelined HMMA GEMM (nbh1 = sign(nb)@W1^T + b1) fused with attn1 --------
// 512 CTAs x 512 threads; CTA = 2 batch elems: M=128, N=256, K=1024 x {hi,lo}
#define ST_A   0           // 128 x 128B = 16384
#define ST_BH  16384       // 256 x 128B = 32768
#define ST_BL  49152       // 256 x 128B = 32768
#define STAGE  81920       // per-stage bytes; 2 stages = 163840
#define SM_B1  163840      // 256 floats
#define SM_A12 164864      // 256 floats
#define SM_SZ  165888      // 128 floats
#define SM_SRS 166400
#define SM_SRQ 166912
#define SM_SW  167424
#define SM_RED 167936      // 32 floats
#define GEMM_SMEM 168064
#define SD_LD  260         // padded sD row stride (floats)

__global__ void __launch_bounds__(512, 1) k_gemm(const float* __restrict__ nb,
                                                 const float* __restrict__ b1,
                                                 const float* __restrict__ a12) {
    extern __shared__ char dsm[];
    const int tid = threadIdx.x;
    const int lane = tid & 31, wid = tid >> 5;
    const int wm = wid >> 2;          // 0..3  (32-row slab)
    const int wn = wid & 3;           // 0..3  (64-col slab)
    const int blk = blockIdx.x;

    const uint32_t sbase = smem_u32(dsm);

    if (tid < 256) {
        ((float*)(dsm + SM_B1))[tid]  = b1[tid];
        ((float*)(dsm + SM_A12))[tid] = a12[tid];
    }

    // ---- per-thread ldmatrix address bases (pre-swizzled; XOR kb later) ----
    uint32_t a_base[2];
    #pragma unroll
    for (int mt = 0; mt < 2; ++mt) {
        uint32_t off = (uint32_t)(((wm << 5) + (mt << 4) + (lane & 15)) * 128 + (lane & 16));
        a_base[mt] = SWZ(off);
    }
    uint32_t b_base[4];
    {
        int nr = (wn << 6) + (lane & 7) + ((lane & 16) >> 1);
        uint32_t off = (uint32_t)(nr * 128 + ((lane & 8) << 1));
        uint32_t s0 = SWZ(off);
        #pragma unroll
        for (int g = 0; g < 4; ++g) b_base[g] = s0 + ((uint32_t)g << 11);
    }

    float acc[2][8][4];
    #pragma unroll
    for (int mt = 0; mt < 2; ++mt)
        #pragma unroll
        for (int nt = 0; nt < 8; ++nt)
            #pragma unroll
            for (int e = 0; e < 4; ++e) acc[mt][nt][e] = 0.f;

    // A-tile loader: 128 rows x 64 cols fp32 -> 16 floats/thread, packed to 8 u32
    const float* Ab = nb + (size_t)blk * 128 * F_;
    const int arow = tid >> 2;                 // 0..127
    const int acs  = (tid & 3) << 4;           // 0,16,32,48
    const uint32_t a_st0 = SWZ((uint32_t)(arow * 128 + (acs << 1)));
    const uint32_t a_st1 = SWZ((uint32_t)(arow * 128 + (acs << 1) + 16));

    uint32_t uA[8];
    auto loadA = [&](int c) {
        const float* ap = Ab + (size_t)arow * F_ + c * 64 + acs;
        float4 v0 = *reinterpret_cast<const float4*>(ap);
        float4 v1 = *reinterpret_cast<const float4*>(ap + 4);
        float4 v2 = *reinterpret_cast<const float4*>(ap + 8);
        float4 v3 = *reinterpret_cast<const float4*>(ap + 12);
        uA[0] = pack2(v0.x, v0.y); uA[1] = pack2(v0.z, v0.w);
        uA[2] = pack2(v1.x, v1.y); uA[3] = pack2(v1.z, v1.w);
        uA[4] = pack2(v2.x, v2.y); uA[5] = pack2(v2.z, v2.w);
        uA[6] = pack2(v3.x, v3.y); uA[7] = pack2(v3.z, v3.w);
    };
    auto storeA = [&](int buf) {
        char* st = dsm + buf * STAGE + ST_A;
        *reinterpret_cast<uint4*>(st + a_st0) = make_uint4(uA[0], uA[1], uA[2], uA[3]);
        *reinterpret_cast<uint4*>(st + a_st1) = make_uint4(uA[4], uA[5], uA[6], uA[7]);
    };
    // B-tile loader via cp.async: hi+lo = 4096 16B lines / 512 threads = 8 each
    auto loadB = [&](int c, int buf) {
        const uint32_t stg = sbase + buf * STAGE;
        const int k0 = c * 64;
        #pragma unroll
        for (int i = 0; i < 8; ++i) {
            int idx = tid + (i << 9);           // 0..4095
            int part = idx >> 11;                // 0 = hi, 1 = lo
            int j = idx & 2047;
            int row = j >> 3, seg = j & 7;
            uint32_t dst = stg + (part ? ST_BL : ST_BH) + SWZ((uint32_t)(row * 128 + seg * 16));
            const __nv_bfloat16* src = (part ? g_W1lo : g_W1hi) + (size_t)row * F_ + k0 + seg * 8;
            cp_async16(dst, src);
        }
        CP_COMMIT();
    };

    // ---- prologue: fill both stages ----
    loadA(0); storeA(0); loadB(0, 0);
    loadA(1); storeA(1); loadB(1, 1);
    CP_WAIT1();
    __syncthreads();

    #pragma unroll 1
    for (int c = 0; c < 16; ++c) {
        const int buf = c & 1;
        const uint32_t aS  = sbase + buf * STAGE + ST_A;
        const uint32_t bhS = sbase + buf * STAGE + ST_BH;
        const uint32_t blS = sbase + buf * STAGE + ST_BL;

        if (c + 2 < 16) loadA(c + 2);   // issue globals before compute (latency overlap)

        #pragma unroll
        for (int ks = 0; ks < 4; ++ks) {
            const uint32_t kb = (uint32_t)ks << 5;
            uint32_t ra[2][4];
            ldsm4(ra[0], aS + (a_base[0] ^ kb));
            ldsm4(ra[1], aS + (a_base[1] ^ kb));
            #pragma unroll
            for (int g = 0; g < 4; ++g) {
                uint32_t t4[4];
                ldsm4(t4, bhS + (b_base[g] ^ kb));
                mma_bf16(acc[0][2*g],   ra[0], &t4[0]);
                mma_bf16(acc[0][2*g+1], ra[0], &t4[2]);
                mma_bf16(acc[1][2*g],   ra[1], &t4[0]);
                mma_bf16(acc[1][2*g+1], ra[1], &t4[2]);
            }
            #pragma unroll
            for (int g = 0; g < 4; ++g) {
                uint32_t t4[4];
                ldsm4(t4, blS + (b_base[g] ^ kb));
                mma_bf16(acc[0][2*g],   ra[0], &t4[0]);
                mma_bf16(acc[0][2*g+1], ra[0], &t4[2]);
                mma_bf16(acc[1][2*g],   ra[1], &t4[0]);
                mma_bf16(acc[1][2*g+1], ra[1], &t4[2]);
            }
        }
        __syncthreads();                 // done reading stage[buf]
        if (c + 2 < 16) {
            storeA(buf);                 // A(c+2) -> stage[buf]
            loadB(c + 2, buf);
            CP_WAIT1();                  // stage[buf^1] (chunk c+1) B complete
        } else {
            CP_WAIT0();
        }
        __syncthreads();
    }

    // ---------------- fused attn1 epilogue (2 batch elems) ----------------
    float* sD = (float*)dsm;                       // [128][SD_LD], aliases stages
    const float* b1s  = (const float*)(dsm + SM_B1);
    const float* a12s = (const float*)(dsm + SM_A12);
    float* sz  = (float*)(dsm + SM_SZ);
    float* srs = (float*)(dsm + SM_SRS);
    float* srq = (float*)(dsm + SM_SRQ);
    float* sW  = (float*)(dsm + SM_SW);
    float* sred = (float*)(dsm + SM_RED);

    {
        const int g8 = lane >> 2, tq = lane & 3;
        #pragma unroll
        for (int mt = 0; mt < 2; ++mt) {
            int row = (wm << 5) + (mt << 4) + g8;
            #pragma unroll
            for (int nt = 0; nt < 8; ++nt) {
                int col = (wn << 6) + (nt << 3) + (tq << 1);
                sD[row * SD_LD + col]           = acc[mt][nt][0] + b1s[col];
                sD[row * SD_LD + col + 1]       = acc[mt][nt][1] + b1s[col + 1];
                sD[(row + 8) * SD_LD + col]     = acc[mt][nt][2] + b1s[col];
                sD[(row + 8) * SD_LD + col + 1] = acc[mt][nt][3] + b1s[col + 1];
            }
        }
    }
    __syncthreads();

    // row stats: 4 threads per row (128 rows x 4 = 512)
    {
        const int r = tid >> 2, ph = tid & 3;
        float rs = 0.f, rq = 0.f, zz = 0.f;
        #pragma unroll 8
        for (int j = 0; j < 64; ++j) {
            int cc = ph + 4 * j;
            float v = sD[r * SD_LD + cc];
            rs += v; rq += v * v; zz += v * a12s[cc];
        }
        rs += __shfl_xor_sync(0xffffffffu, rs, 1); rs += __shfl_xor_sync(0xffffffffu, rs, 2);
        rq += __shfl_xor_sync(0xffffffffu, rq, 1); rq += __shfl_xor_sync(0xffffffffu, rq, 2);
        zz += __shfl_xor_sync(0xffffffffu, zz, 1); zz += __shfl_xor_sync(0xffffffffu, zz, 2);
        if (ph == 0) {
            srs[r] = rs; srq[r] = rq;
            float l = zz + g_t1[2 * blk + (r >> 6)];
            sz[r] = (l > 0.f) ? l : ALPHA_ * l;
        }
    }
    __syncthreads();

    if (tid < 128) {
        int b = tid >> 6;
        float mx = -1e30f;
        for (int j = 0; j < 64; ++j) mx = fmaxf(mx, sz[b * 64 + j]);
        float den = 0.f;
        for (int j = 0; j < 64; ++j) den += expf(sz[b * 64 + j] - mx);
        sW[tid] = expf(sz[tid] - mx) / den;
        if ((tid & 63) == 0) {
            float s = 0.f, q = 0.f;
            for (int j = 0; j < 64; ++j) { s += srs[b * 64 + j]; q += srq[b * 64 + j]; }
            g_bsum[2 * blk + b] = s;
            g_bsumsq[2 * blk + b] = q;
        }
    }
    __syncthreads();

    // x1[h] = sum_n sW[n]*D[n][h]; also write nbh1 to global
    {
        const int b = tid >> 8, h = tid & 255;   // 512 threads cover 2 x 256
        float accx = 0.f;
        float* gout = g_nbh1 + (size_t)(2 * blk + b) * (Nn * H1_);
        const float* sDb = sD + (b * 64) * SD_LD;
        const float* sWb = sW + b * 64;
        #pragma unroll 8
        for (int n = 0; n < Nn; ++n) {
            float v = sDb[n * SD_LD + h];
            gout[n * H1_ + h] = v;
            accx += sWb[n] * v;
        }
        g_x1[(size_t)(2 * blk + b) * H1_ + h] = accx;
        float ts = blockSumB(accx, sred);
        if (tid == 0) atomicAdd(&g_scalars[3], ts);
        float tq2 = blockSumB(accx * accx, sred);
        if (tid == 0) atomicAdd(&g_scalars[4], tq2);
    }
}

// -------- K4: BN+ReLU + layer-2 attention; y[b,:] = sum_n A2 * relu(bn(nbh1)) --------
__global__ void __launch_bounds__(256) k_attn2(const float* __restrict__ g1p,
                                               const float* __restrict__ be1p) {
    int b = blockIdx.x;
    int h = threadIdx.x;
    int lane = h & 31, warp = h >> 5;
    __shared__ float swa[H1_];
    __shared__ float sS[Nn];
    __shared__ float sW[Nn];
    __shared__ float sred[32];
    swa[h] = g_wa22h[h];
    __syncthreads();

    float g1 = g1p[0], be1 = be1p[0];
    const float invb = 1.f / (float)(Nn * H1_);
    float mb = g_bsum[b] * invb;
    float vb = g_bsumsq[b] * invb - mb * mb;
    float ab = g1 * rsqrtf(vb + BN_EPS_);
    float bb = be1 - ab * mb;
    const float invx = 1.f / (float)(B_ * H1_);
    float mxm = g_scalars[3] * invx;
    float vx  = g_scalars[4] * invx - mxm * mxm;
    float ax  = g1 * rsqrtf(vx + BN_EPS_);
    float bx  = be1 - ax * mxm;

    float u = fmaxf(ax * g_x1[b * H1_ + h] + bx, 0.f);
    float t2 = blockSumB(u * g_wa21h[h], sred) + g_scalars[1];

    const float* base = g_nbh1 + (size_t)b * (Nn * H1_);
    const float c22 = g_scalars[2];
    for (int ni = 0; ni < 8; ++ni) {
        int n = warp * 8 + ni;
        const float4* row4 = reinterpret_cast<const float4*>(base + n * H1_);
        float z = 0.f;
        #pragma unroll
        for (int j = 0; j < 2; ++j) {
            int i = lane + 32 * j;
            float4 v = row4[i];
            int c0 = 4 * i;
            z += fmaxf(ab * v.x + bb, 0.f) * swa[c0];
            z += fmaxf(ab * v.y + bb, 0.f) * swa[c0 + 1];
            z += fmaxf(ab * v.z + bb, 0.f) * swa[c0 + 2];
            z += fmaxf(ab * v.w + bb, 0.f) * swa[c0 + 3];
        }
        #pragma unroll
        for (int o = 16; o; o >>= 1) z += __shfl_xor_sync(0xffffffffu, z, o);
        if (lane == 0) sS[n] = z + c22;
    }
    __syncthreads();
    if (h < Nn) {
        float s = t2 + sS[h];
        sS[h] = (s > 0.f) ? s : ALPHA_ * s;
    }
    __syncthreads();
    float mx = -1e30f;
    for (int n = 0; n < Nn; ++n) mx = fmaxf(mx, sS[n]);
    float den = 0.f;
    for (int n = 0; n < Nn; ++n) den += expf(sS[n] - mx);
    if (h < Nn) sW[h] = expf(sS[h] - mx) / den;
    __syncthreads();

    float y = 0.f;
    #pragma unroll 8
    for (int n = 0; n < Nn; ++n) {
        float v = fmaxf(ab * base[n * H1_ + h] + bb, 0.f);
        y += sW[n] * v;
    }
    g_y[b * H1_ + h] = y;
}

// -------- K5: x2 = y @ W2^T + b2 --------
__global__ void __launch_bounds__(128) k_lin2(const float* __restrict__ b2) {
    int bb = blockIdx.x * 8;
    int h2 = threadIdx.x;
    __shared__ float sy[8 * H1_];
    __shared__ float sred[32];
    for (int i = h2; i < 8 * H1_; i += 128) sy[i] = g_y[(size_t)bb * H1_ + i];
    __syncthreads();
    float acc[8];
    #pragma unroll
    for (int i = 0; i < 8; ++i) acc[i] = 0.f;
    for (int k = 0; k < H1_; ++k) {
        float w = g_W2T[k * H2_ + h2];
        #pragma unroll
        for (int i = 0; i < 8; ++i) acc[i] += sy[i * H1_ + k] * w;
    }
    float b2v = b2[h2];
    float ls = 0.f, lq = 0.f;
    #pragma unroll
    for (int i = 0; i < 8; ++i) {
        float s = acc[i] + b2v;
        g_x2[(size_t)(bb + i) * H2_ + h2] = s;
        ls += s; lq += s * s;
    }
    float a = blockSumB(ls, sred);
    if (h2 == 0) atomicAdd(&g_scalars[5], a);
    float q = blockSumB(lq, sred);
    if (h2 == 0) atomicAdd(&g_scalars[6], q);
}

// -------- K6: logits = relu(bn(x2)) @ Wl^T + bl --------
__global__ void __launch_bounds__(128) k_final(const float* __restrict__ g2p,
                                               const float* __restrict__ be2p,
                                               const float* __restrict__ bl,
                                               float* __restrict__ out) {
    int bb = blockIdx.x * 8;
    int c = threadIdx.x;
    const float inv2 = 1.f / (float)(B_ * H2_);
    float m = g_scalars[5] * inv2;
    float v = g_scalars[6] * inv2 - m * m;
    float a2 = g2p[0] * rsqrtf(v + BN_EPS_);
    float s2 = be2p[0] - a2 * m;
    __shared__ float sx[8 * H2_];
    #pragma unroll
    for (int i = 0; i < 8; ++i) {
        float t = a2 * g_x2[(size_t)(bb + i) * H2_ + c] + s2;
        sx[i * H2_ + c] = fmaxf(t, 0.f);
    }
    __syncthreads();
    float acc[8];
    #pragma unroll
    for (int i = 0; i < 8; ++i) acc[i] = 0.f;
    for (int k = 0; k < H2_; ++k) {
        float w = g_WlT[k * NC_ + c];
        #pragma unroll
        for (int i = 0; i < 8; ++i) acc[i] += sx[i * H2_ + k] * w;
    }
    float blc = bl[c];
    #pragma unroll
    for (int i = 0; i < 8; ++i) out[(size_t)(bb + i) * NC_ + c] = acc[i] + blc;
}

extern "C" void kernel_launch(void* const* d_in, const int* in_sizes, int n_in,
                              void* d_out, int out_size) {
    const float* x   = (const float*)d_in[0];
    const float* nb  = (const float*)d_in[1];
    const float* W1  = (const float*)d_in[2];
    const float* b1  = (const float*)d_in[3];
    const float* a11 = (const float*)d_in[4];
    const float* a12 = (const float*)d_in[5];
    const float* g1  = (const float*)d_in[6];
    const float* be1 = (const float*)d_in[7];
    const float* W2  = (const float*)d_in[8];
    const float* b2  = (const float*)d_in[9];
    const float* a21 = (const float*)d_in[10];
    const float* a22 = (const float*)d_in[11];
    const float* g2  = (const float*)d_in[12];
    const float* be2 = (const float*)d_in[13];
    const float* Wl  = (const float*)d_in[14];
    const float* bl  = (const float*)d_in[15];
    float* out = (float*)d_out;

    static int smem_set = 0;
    if (!smem_set) {
        cudaFuncSetAttribute(k_gemm, cudaFuncAttributeMaxDynamicSharedMemorySize, GEMM_SMEM);
        smem_set = 1;
    }

    k_pre<<<32, 256>>>(W1, b1, a11, W2, b2, a21, a22, Wl);
    k_t1<<<B_, 256>>>(x);
    k_gemm<<<B_ / 2, 512, GEMM_SMEM>>>(nb, b1, a12);
    k_attn2<<<B_, 256>>>(g1, be1);
    k_lin2<<<B_ / 8, 128>>>(b2);
    k_final<<<B_ / 8, 128>>>(g2, be2, bl, out);
}

// round 14
// speedup vs baseline: 3.4464x; 1.2623x over previous
#include <cuda_runtime.h>
#include <cuda_fp16.h>
#include <cstdint>

// Shapes (fixed by the problem)
#define B_  1024
#define Nn  64
#define F_  1024
#define H1_ 256
#define H2_ 128
#define NC_ 128
#define R_  65536          // B_*Nn
#define ALPHA_ 0.2f
#define BN_EPS_ 1e-5f

// -------- scratch (static __device__ arrays; no allocation) --------
__device__ float g_v[R_ * H1_];        // 64 MB: relu(bn(nbh1)) per-neighbor features
__device__ float g_x1[B_ * H1_];       // layer-1 output x (pre-BN)
__device__ float g_y[B_ * H1_];        // attention-weighted BN'd neighbors (layer 2)
__device__ float g_x2[B_ * H2_];       // layer-2 output x (pre-BN)
__device__ float g_t1[B_];             // self attention score part, layer 1
__device__ float g_s2[B_ * Nn];        // layer-2 neighbor scores (pre-t2)
__device__ float g_wa11f[F_];          // W1^T @ a11
__device__ float g_wa21h[H1_];         // W2^T @ a21
__device__ float g_wa22h[H1_];         // W2^T @ a22
__device__ float g_W2T[H1_ * H2_];     // W2 transposed [h1][h2]
__device__ float g_WlT[H2_ * NC_];     // Wl transposed [h2][c]
__device__ float g_scalars[8];         // 0:c11 1:c21 2:c22 3:xsum 4:xsq 5:x2sum 6:x2sq
__device__ __half g_W1h[H1_ * F_];     // fp16 W1

__device__ __forceinline__ float sgnf(float v) {
    return (v > 0.f) ? 1.f : ((v < 0.f) ? -1.f : 0.f);
}
__device__ __forceinline__ uint32_t sgnh(float v) {
    return (v > 0.f) ? 0x3C00u : ((v < 0.f) ? 0xBC00u : 0u);   // fp16 +-1.0
}
__device__ __forceinline__ uint32_t pack2(float x, float y) {
    return sgnh(x) | (sgnh(y) << 16);
}

// block-wide sum with broadcast; sred must hold >= 32 floats; result in sred[16]
__device__ __forceinline__ float blockSumB(float v, float* sred) {
    const unsigned FULL = 0xffffffffu;
    #pragma unroll
    for (int o = 16; o; o >>= 1) v += __shfl_xor_sync(FULL, v, o);
    int lane = threadIdx.x & 31, wid = threadIdx.x >> 5;
    __syncthreads();
    if (lane == 0) sred[wid] = v;
    __syncthreads();
    if (wid == 0) {
        float t = (lane * 32 < (int)blockDim.x) ? sred[lane] : 0.f;
        #pragma unroll
        for (int o = 16; o; o >>= 1) t += __shfl_xor_sync(FULL, t, o);
        if (lane == 0) sred[16] = t;
    }
    __syncthreads();
    return sred[16];
}

// ================= mma.sync helpers =================
__device__ __forceinline__ uint32_t smem_u32(const void* p) {
    uint32_t a;
    asm("{ .reg .u64 t; cvta.to.shared.u64 t, %1; cvt.u32.u64 %0, t; }" : "=r"(a) : "l"(p));
    return a;
}
__device__ __forceinline__ void ldsm4(uint32_t* r, uint32_t addr) {
    asm volatile("ldmatrix.sync.aligned.m8n8.x4.shared.b16 {%0,%1,%2,%3}, [%4];"
                 : "=r"(r[0]), "=r"(r[1]), "=r"(r[2]), "=r"(r[3]) : "r"(addr));
}
__device__ __forceinline__ void mma_f16(float* d, const uint32_t* a, const uint32_t* b) {
    asm volatile(
        "mma.sync.aligned.m16n8k16.row.col.f32.f16.f16.f32 "
        "{%0,%1,%2,%3}, {%4,%5,%6,%7}, {%8,%9}, {%0,%1,%2,%3};"
        : "+f"(d[0]), "+f"(d[1]), "+f"(d[2]), "+f"(d[3])
        : "r"(a[0]), "r"(a[1]), "r"(a[2]), "r"(a[3]), "r"(b[0]), "r"(b[1]));
}
__device__ __forceinline__ void cp_async16(uint32_t dst, const void* src) {
    asm volatile("cp.async.cg.shared.global [%0], [%1], 16;" :: "r"(dst), "l"(src));
}
#define CP_COMMIT() asm volatile("cp.async.commit_group;" ::: "memory")
#define CP_WAIT1()  asm volatile("cp.async.wait_group 1;" ::: "memory")
#define CP_WAIT0()  asm volatile("cp.async.wait_group 0;" ::: "memory")
#define SWZ(o) ((o) ^ (((o) >> 3) & 0x70))

// -------- K0: precompute folded vectors, fp16 W1, transposes, constants --------
__global__ void __launch_bounds__(256) k_pre(const float* __restrict__ W1,
                                             const float* __restrict__ b1,
                                             const float* __restrict__ a11,
                                             const float* __restrict__ W2,
                                             const float* __restrict__ b2,
                                             const float* __restrict__ a21,
                                             const float* __restrict__ a22,
                                             const float* __restrict__ Wl) {
    int t = blockIdx.x * 256 + threadIdx.x;   // 0..8191 (32 blocks)
    if (t < F_) {
        float s = 0.f;
        for (int h = 0; h < H1_; ++h) s += a11[h] * W1[h * F_ + t];
        g_wa11f[t] = s;
    }
    if (t < H1_) {
        float s21 = 0.f, s22 = 0.f;
        for (int h2 = 0; h2 < H2_; ++h2) {
            float w = W2[h2 * H1_ + t];
            s21 += a21[h2] * w;
            s22 += a22[h2] * w;
        }
        g_wa21h[t] = s21;
        g_wa22h[t] = s22;
    }
    for (int i = t; i < H1_ * F_; i += 8192)
        g_W1h[i] = __float2half_rn(W1[i]);
    for (int i = t; i < H1_ * H2_; i += 8192) {
        int k = i / H2_, h2 = i % H2_;
        g_W2T[i] = W2[h2 * H1_ + k];
    }
    for (int i = t; i < H2_ * NC_; i += 8192) {
        int h2 = i / NC_, c = i % NC_;
        g_WlT[i] = Wl[c * H2_ + h2];
    }
    if (t == 0) {
        float c11 = 0.f;
        for (int h = 0; h < H1_; ++h) c11 += b1[h] * a11[h];
        float c21 = 0.f, c22 = 0.f;
        for (int h = 0; h < H2_; ++h) { c21 += b2[h] * a21[h]; c22 += b2[h] * a22[h]; }
        g_scalars[0] = c11; g_scalars[1] = c21; g_scalars[2] = c22;
        g_scalars[3] = 0.f; g_scalars[4] = 0.f; g_scalars[5] = 0.f; g_scalars[6] = 0.f;
    }
}

// -------- K1: t1[b] = sign(x[b,:]) . wa11f + c11 --------
__global__ void __launch_bounds__(256) k_t1(const float* __restrict__ x) {
    __shared__ float sred[32];
    int b = blockIdx.x;
    float s = 0.f;
    for (int f = threadIdx.x; f < F_; f += 256)
        s += sgnf(x[(size_t)b * F_ + f]) * g_wa11f[f];
    float tot = blockSumB(s, sred);
    if (threadIdx.x == 0) g_t1[b] = tot + g_scalars[0];
}

// -------- K2: fp16 HMMA GEMM fused with attn1 + layer-1 BN + layer-2 scores --------
// 512 CTAs x 512 threads; CTA = 2 batch elems: M=128, N=256, K=1024
#define ST_A   0           // 128 x 128B = 16384
#define ST_B   16384       // 256 x 128B = 32768
#define STAGE  49152       // per-stage bytes; 2 stages = 98304
#define SM_B1   133120     // after sD (128*260*4 = 133120)
#define SM_A12  134144
#define SM_WA22 135168
#define SM_SZ   136192     // 128 floats
#define SM_SRS  136704
#define SM_SRQ  137216
#define SM_SW   137728
#define SM_AB   138240     // sab[2], sbb[2]
#define SM_RED  138272     // 32 floats
#define GEMM_SMEM 138400
#define SD_LD  260         // padded sD row stride (floats)

__global__ void __launch_bounds__(512, 1) k_gemm(const float* __restrict__ nb,
                                                 const float* __restrict__ b1,
                                                 const float* __restrict__ a12,
                                                 const float* __restrict__ g1p,
                                                 const float* __restrict__ be1p) {
    extern __shared__ char dsm[];
    const int tid = threadIdx.x;
    const int lane = tid & 31, wid = tid >> 5;
    const int wm = wid >> 2;          // 0..3  (32-row slab)
    const int wn = wid & 3;           // 0..3  (64-col slab)
    const int blk = blockIdx.x;

    const uint32_t sbase = smem_u32(dsm);

    if (tid < 256) {
        ((float*)(dsm + SM_B1))[tid]   = b1[tid];
        ((float*)(dsm + SM_A12))[tid]  = a12[tid];
        ((float*)(dsm + SM_WA22))[tid] = g_wa22h[tid];
    }

    // ---- per-thread ldmatrix address bases (pre-swizzled; XOR kb later) ----
    uint32_t a_base[2];
    #pragma unroll
    for (int mt = 0; mt < 2; ++mt) {
        uint32_t off = (uint32_t)(((wm << 5) + (mt << 4) + (lane & 15)) * 128 + (lane & 16));
        a_base[mt] = SWZ(off);
    }
    uint32_t b_base[4];
    {
        int nr = (wn << 6) + (lane & 7) + ((lane & 16) >> 1);
        uint32_t off = (uint32_t)(nr * 128 + ((lane & 8) << 1));
        uint32_t s0 = SWZ(off);
        #pragma unroll
        for (int g = 0; g < 4; ++g) b_base[g] = s0 + ((uint32_t)g << 11);
    }

    float acc[2][8][4];
    #pragma unroll
    for (int mt = 0; mt < 2; ++mt)
        #pragma unroll
        for (int nt = 0; nt < 8; ++nt)
            #pragma unroll
            for (int e = 0; e < 4; ++e) acc[mt][nt][e] = 0.f;

    // A-tile loader: 128 rows x 64 cols fp32 -> 16 floats/thread, packed to 8 u32
    const float* Ab = nb + (size_t)blk * 128 * F_;
    const int arow = tid >> 2;                 // 0..127
    const int acs  = (tid & 3) << 4;           // 0,16,32,48
    const uint32_t a_st0 = SWZ((uint32_t)(arow * 128 + (acs << 1)));
    const uint32_t a_st1 = SWZ((uint32_t)(arow * 128 + (acs << 1) + 16));

    uint32_t uA[8];
    auto loadA = [&](int c) {
        const float* ap = Ab + (size_t)arow * F_ + c * 64 + acs;
        float4 v0 = *reinterpret_cast<const float4*>(ap);
        float4 v1 = *reinterpret_cast<const float4*>(ap + 4);
        float4 v2 = *reinterpret_cast<const float4*>(ap + 8);
        float4 v3 = *reinterpret_cast<const float4*>(ap + 12);
        uA[0] = pack2(v0.x, v0.y); uA[1] = pack2(v0.z, v0.w);
        uA[2] = pack2(v1.x, v1.y); uA[3] = pack2(v1.z, v1.w);
        uA[4] = pack2(v2.x, v2.y); uA[5] = pack2(v2.z, v2.w);
        uA[6] = pack2(v3.x, v3.y); uA[7] = pack2(v3.z, v3.w);
    };
    auto storeA = [&](int buf) {
        char* st = dsm + buf * STAGE + ST_A;
        *reinterpret_cast<uint4*>(st + a_st0) = make_uint4(uA[0], uA[1], uA[2], uA[3]);
        *reinterpret_cast<uint4*>(st + a_st1) = make_uint4(uA[4], uA[5], uA[6], uA[7]);
    };
    // B-tile loader via cp.async: 2048 16B lines / 512 threads = 4 each
    auto loadB = [&](int c, int buf) {
        const uint32_t stg = sbase + buf * STAGE + ST_B;
        const int k0 = c * 64;
        #pragma unroll
        for (int i = 0; i < 4; ++i) {
            int j = tid + (i << 9);             // 0..2047
            int row = j >> 3, seg = j & 7;
            uint32_t dst = stg + SWZ((uint32_t)(row * 128 + seg * 16));
            const __half* src = g_W1h + (size_t)row * F_ + k0 + seg * 8;
            cp_async16(dst, src);
        }
        CP_COMMIT();
    };

    // ---- prologue: fill both stages ----
    loadA(0); storeA(0); loadB(0, 0);
    loadA(1); storeA(1); loadB(1, 1);
    CP_WAIT1();
    __syncthreads();

    #pragma unroll 1
    for (int c = 0; c < 16; ++c) {
        const int buf = c & 1;
        const uint32_t aS = sbase + buf * STAGE + ST_A;
        const uint32_t bS = sbase + buf * STAGE + ST_B;

        if (c + 2 < 16) loadA(c + 2);   // issue globals before compute

        #pragma unroll
        for (int ks = 0; ks < 4; ++ks) {
            const uint32_t kb = (uint32_t)ks << 5;
            uint32_t ra[2][4];
            ldsm4(ra[0], aS + (a_base[0] ^ kb));
            ldsm4(ra[1], aS + (a_base[1] ^ kb));
            #pragma unroll
            for (int g = 0; g < 4; ++g) {
                uint32_t t4[4];
                ldsm4(t4, bS + (b_base[g] ^ kb));
                mma_f16(acc[0][2*g],   ra[0], &t4[0]);
                mma_f16(acc[0][2*g+1], ra[0], &t4[2]);
                mma_f16(acc[1][2*g],   ra[1], &t4[0]);
                mma_f16(acc[1][2*g+1], ra[1], &t4[2]);
            }
        }
        __syncthreads();                 // done reading stage[buf]
        if (c + 2 < 16) {
            storeA(buf);
            loadB(c + 2, buf);
            CP_WAIT1();
        } else {
            CP_WAIT0();
        }
        __syncthreads();
    }

    // ---------------- fused epilogue (2 batch elems) ----------------
    float* sD = (float*)dsm;                       // [128][SD_LD], aliases stages
    const float* b1s  = (const float*)(dsm + SM_B1);
    const float* a12s = (const float*)(dsm + SM_A12);
    const float* wa22 = (const float*)(dsm + SM_WA22);
    float* sz  = (float*)(dsm + SM_SZ);
    float* srs = (float*)(dsm + SM_SRS);
    float* srq = (float*)(dsm + SM_SRQ);
    float* sW  = (float*)(dsm + SM_SW);
    float* sab = (float*)(dsm + SM_AB);            // [0..1]=ab, [2..3]=bb
    float* sred = (float*)(dsm + SM_RED);

    {
        const int g8 = lane >> 2, tq = lane & 3;
        #pragma unroll
        for (int mt = 0; mt < 2; ++mt) {
            int row = (wm << 5) + (mt << 4) + g8;
            #pragma unroll
            for (int nt = 0; nt < 8; ++nt) {
                int col = (wn << 6) + (nt << 3) + (tq << 1);
                sD[row * SD_LD + col]           = acc[mt][nt][0] + b1s[col];
                sD[row * SD_LD + col + 1]       = acc[mt][nt][1] + b1s[col + 1];
                sD[(row + 8) * SD_LD + col]     = acc[mt][nt][2] + b1s[col];
                sD[(row + 8) * SD_LD + col + 1] = acc[mt][nt][3] + b1s[col + 1];
            }
        }
    }
    __syncthreads();

    // pass A: row stats (4 threads per row): BN sums + attn1 scores
    {
        const int r = tid >> 2, ph = tid & 3;
        float rs = 0.f, rq = 0.f, zz = 0.f;
        #pragma unroll 8
        for (int j = 0; j < 64; ++j) {
            int cc = ph + 4 * j;
            float v = sD[r * SD_LD + cc];
            rs += v; rq += v * v; zz += v * a12s[cc];
        }
        rs += __shfl_xor_sync(0xffffffffu, rs, 1); rs += __shfl_xor_sync(0xffffffffu, rs, 2);
        rq += __shfl_xor_sync(0xffffffffu, rq, 1); rq += __shfl_xor_sync(0xffffffffu, rq, 2);
        zz += __shfl_xor_sync(0xffffffffu, zz, 1); zz += __shfl_xor_sync(0xffffffffu, zz, 2);
        if (ph == 0) {
            srs[r] = rs; srq[r] = rq;
            float l = zz + g_t1[2 * blk + (r >> 6)];
            sz[r] = (l > 0.f) ? l : ALPHA_ * l;
        }
    }
    __syncthreads();

    // softmax weights (attn1) + per-b BN coefficients ab, bb
    if (tid < 128) {
        int b = tid >> 6;
        float mx = -1e30f;
        for (int j = 0; j < 64; ++j) mx = fmaxf(mx, sz[b * 64 + j]);
        float den = 0.f;
        for (int j = 0; j < 64; ++j) den += expf(sz[b * 64 + j] - mx);
        sW[tid] = expf(sz[tid] - mx) / den;
        if ((tid & 63) == 0) {
            float s = 0.f, q = 0.f;
            for (int j = 0; j < 64; ++j) { s += srs[b * 64 + j]; q += srq[b * 64 + j]; }
            const float invb = 1.f / (float)(Nn * H1_);
            float mb = s * invb;
            float vb = q * invb - mb * mb;
            float ab = g1p[0] * rsqrtf(vb + BN_EPS_);
            sab[b] = ab;
            sab[2 + b] = be1p[0] - ab * mb;
        }
    }
    __syncthreads();

    // pass B: layer-2 scores s2[n] = sum_h relu(ab*D+bb) * wa22[h] + c22
    {
        const int r = tid >> 2, ph = tid & 3;
        const float ab = sab[r >> 6], bb = sab[2 + (r >> 6)];
        float z2 = 0.f;
        #pragma unroll 8
        for (int j = 0; j < 64; ++j) {
            int cc = ph + 4 * j;
            float v = fmaxf(ab * sD[r * SD_LD + cc] + bb, 0.f);
            z2 += v * wa22[cc];
        }
        z2 += __shfl_xor_sync(0xffffffffu, z2, 1);
        z2 += __shfl_xor_sync(0xffffffffu, z2, 2);
        if (ph == 0)
            g_s2[(size_t)(2 * blk + (r >> 6)) * Nn + (r & 63)] = z2 + g_scalars[2];
    }

    // pass C: x1 (raw D x attn1 weights) + write v = relu(ab*D+bb) to global
    {
        const int b = tid >> 8, h = tid & 255;   // 512 threads cover 2 x 256
        const float ab = sab[b], bb = sab[2 + b];
        float accx = 0.f;
        float* gout = g_v + (size_t)(2 * blk + b) * (Nn * H1_);
        const float* sDb = sD + (b * 64) * SD_LD;
        const float* sWb = sW + b * 64;
        #pragma unroll 8
        for (int n = 0; n < Nn; ++n) {
            float raw = sDb[n * SD_LD + h];
            gout[n * H1_ + h] = fmaxf(ab * raw + bb, 0.f);
            accx += sWb[n] * raw;
        }
        g_x1[(size_t)(2 * blk + b) * H1_ + h] = accx;
        float ts = blockSumB(accx, sred);
        if (tid == 0) atomicAdd(&g_scalars[3], ts);
        float tq2 = blockSumB(accx * accx, sred);
        if (tid == 0) atomicAdd(&g_scalars[4], tq2);
    }
}

// -------- K4: layer-2 softmax + weighted sum (single read of v) --------
__global__ void __launch_bounds__(256) k_attn2(const float* __restrict__ g1p,
                                               const float* __restrict__ be1p) {
    int b = blockIdx.x;
    int h = threadIdx.x;
    __shared__ float sS[Nn];
    __shared__ float sW[Nn];
    __shared__ float sred[32];

    const float invx = 1.f / (float)(B_ * H1_);
    float mxm = g_scalars[3] * invx;
    float vx  = g_scalars[4] * invx - mxm * mxm;
    float ax  = g1p[0] * rsqrtf(vx + BN_EPS_);
    float bx  = be1p[0] - ax * mxm;

    float u = fmaxf(ax * g_x1[b * H1_ + h] + bx, 0.f);
    float t2 = blockSumB(u * g_wa21h[h], sred) + g_scalars[1];

    if (h < Nn) {
        float s = t2 + g_s2[(size_t)b * Nn + h];
        sS[h] = (s > 0.f) ? s : ALPHA_ * s;
    }
    __syncthreads();
    float mx = -1e30f;
    for (int n = 0; n < Nn; ++n) mx = fmaxf(mx, sS[n]);
    float den = 0.f;
    for (int n = 0; n < Nn; ++n) den += expf(sS[n] - mx);
    if (h < Nn) sW[h] = expf(sS[h] - mx) / den;
    __syncthreads();

    const float* base = g_v + (size_t)b * (Nn * H1_);
    float y = 0.f;
    #pragma unroll 8
    for (int n = 0; n < Nn; ++n)
        y += sW[n] * base[n * H1_ + h];
    g_y[b * H1_ + h] = y;
}

// -------- K5: x2 = y @ W2^T + b2 --------
__global__ void __launch_bounds__(128) k_lin2(const float* __restrict__ b2) {
    int bb = blockIdx.x * 8;
    int h2 = threadIdx.x;
    __shared__ float sy[8 * H1_];
    __shared__ float sred[32];
    for (int i = h2; i < 8 * H1_; i += 128) sy[i] = g_y[(size_t)bb * H1_ + i];
    __syncthreads();
    float acc[8];
    #pragma unroll
    for (int i = 0; i < 8; ++i) acc[i] = 0.f;
    for (int k = 0; k < H1_; ++k) {
        float w = g_W2T[k * H2_ + h2];
        #pragma unroll
        for (int i = 0; i < 8; ++i) acc[i] += sy[i * H1_ + k] * w;
    }
    float b2v = b2[h2];
    float ls = 0.f, lq = 0.f;
    #pragma unroll
    for (int i = 0; i < 8; ++i) {
        float s = acc[i] + b2v;
        g_x2[(size_t)(bb + i) * H2_ + h2] = s;
        ls += s; lq += s * s;
    }
    float a = blockSumB(ls, sred);
    if (h2 == 0) atomicAdd(&g_scalars[5], a);
    float q = blockSumB(lq, sred);
    if (h2 == 0) atomicAdd(&g_scalars[6], q);
}

// -------- K6: logits = relu(bn(x2)) @ Wl^T + bl --------
__global__ void __launch_bounds__(128) k_final(const float* __restrict__ g2p,
                                               const float* __restrict__ be2p,
                                               const float* __restrict__ bl,
                                               float* __restrict__ out) {
    int bb = blockIdx.x * 8;
    int c = threadIdx.x;
    const float inv2 = 1.f / (float)(B_ * H2_);
    float m = g_scalars[5] * inv2;
    float v = g_scalars[6] * inv2 - m * m;
    float a2 = g2p[0] * rsqrtf(v + BN_EPS_);
    float s2 = be2p[0] - a2 * m;
    __shared__ float sx[8 * H2_];
    #pragma unroll
    for (int i = 0; i < 8; ++i) {
        float t = a2 * g_x2[(size_t)(bb + i) * H2_ + c] + s2;
        sx[i * H2_ + c] = fmaxf(t, 0.f);
    }
    __syncthreads();
    float acc[8];
    #pragma unroll
    for (int i = 0; i < 8; ++i) acc[i] = 0.f;
    for (int k = 0; k < H2_; ++k) {
        float w = g_WlT[k * NC_ + c];
        #pragma unroll
        for (int i = 0; i < 8; ++i) acc[i] += sx[i * H2_ + k] * w;
    }
    float blc = bl[c];
    #pragma unroll
    for (int i = 0; i < 8; ++i) out[(size_t)(bb + i) * NC_ + c] = acc[i] + blc;
}

extern "C" void kernel_launch(void* const* d_in, const int* in_sizes, int n_in,
                              void* d_out, int out_size) {
    const float* x   = (const float*)d_in[0];
    const float* nb  = (const float*)d_in[1];
    const float* W1  = (const float*)d_in[2];
    const float* b1  = (const float*)d_in[3];
    const float* a11 = (const float*)d_in[4];
    const float* a12 = (const float*)d_in[5];
    const float* g1  = (const float*)d_in[6];
    const float* be1 = (const float*)d_in[7];
    const float* W2  = (const float*)d_in[8];
    const float* b2  = (const float*)d_in[9];
    const float* a21 = (const float*)d_in[10];
    const float* a22 = (const float*)d_in[11];
    const float* g2  = (const float*)d_in[12];
    const float* be2 = (const float*)d_in[13];
    const float* Wl  = (const float*)d_in[14];
    const float* bl  = (const float*)d_in[15];
    float* out = (float*)d_out;

    static int smem_set = 0;
    if (!smem_set) {
        cudaFuncSetAttribute(k_gemm, cudaFuncAttributeMaxDynamicSharedMemorySize, GEMM_SMEM);
        smem_set = 1;
    }

    k_pre<<<32, 256>>>(W1, b1, a11, W2, b2, a21, a22, Wl);
    k_t1<<<B_, 256>>>(x);
    k_gemm<<<B_ / 2, 512, GEMM_SMEM>>>(nb, b1, a12, g1, be1);
    k_attn2<<<B_, 256>>>(g1, be1);
    k_lin2<<<B_ / 8, 128>>>(b2);
    k_final<<<B_ / 8, 128>>>(g2, be2, bl, out);
}

// round 15
// speedup vs baseline: 3.9918x; 1.1582x over previous
#include <cuda_runtime.h>
#include <cuda_fp16.h>
#include <cstdint>

// Shapes (fixed by the problem)
#define B_  1024
#define Nn  64
#define F_  1024
#define H1_ 256
#define H2_ 128
#define NC_ 128
#define R_  65536          // B_*Nn
#define ALPHA_ 0.2f
#define BN_EPS_ 1e-5f

// -------- scratch (static __device__ arrays; no allocation) --------
__device__ float g_v[R_ * H1_];        // 64 MB: relu(bn(nbh1)) per-neighbor features
__device__ float g_x1[B_ * H1_];       // layer-1 output x (pre-BN)
__device__ float g_y[B_ * H1_];        // attention-weighted BN'd neighbors (layer 2)
__device__ float g_x2[B_ * H2_];       // layer-2 output x (pre-BN)
__device__ float g_t1[B_];             // self attention score part, layer 1
__device__ float g_s2[B_ * Nn];        // layer-2 neighbor scores (pre-t2)
__device__ float g_wa11f[F_];          // W1^T @ a11
__device__ float g_wa21h[H1_];         // W2^T @ a21
__device__ float g_wa22h[H1_];         // W2^T @ a22
__device__ float g_W2T[H1_ * H2_];     // W2 transposed [h1][h2]
__device__ float g_WlT[H2_ * NC_];     // Wl transposed [h2][c]
__device__ float g_scalars[8];         // 0:c11 1:c21 2:c22 3:xsum 4:xsq 5:x2sum 6:x2sq
__device__ __half g_W1h[H1_ * F_];     // fp16 W1

__device__ __forceinline__ float sgnf(float v) {
    return (v > 0.f) ? 1.f : ((v < 0.f) ? -1.f : 0.f);
}
// branchless: +-1.0h carrying the fp32 sign bit (inputs are continuous -> no exact zeros)
__device__ __forceinline__ uint32_t pack2(float x, float y) {
    uint32_t xb = __float_as_uint(x), yb = __float_as_uint(y);
    return 0x3C003C00u | ((xb >> 16) & 0x8000u) | (yb & 0x80000000u);
}

// block-wide sum with broadcast; sred must hold >= 32 floats; result in sred[16]
__device__ __forceinline__ float blockSumB(float v, float* sred) {
    const unsigned FULL = 0xffffffffu;
    #pragma unroll
    for (int o = 16; o; o >>= 1) v += __shfl_xor_sync(FULL, v, o);
    int lane = threadIdx.x & 31, wid = threadIdx.x >> 5;
    __syncthreads();
    if (lane == 0) sred[wid] = v;
    __syncthreads();
    if (wid == 0) {
        float t = (lane * 32 < (int)blockDim.x) ? sred[lane] : 0.f;
        #pragma unroll
        for (int o = 16; o; o >>= 1) t += __shfl_xor_sync(FULL, t, o);
        if (lane == 0) sred[16] = t;
    }
    __syncthreads();
    return sred[16];
}

// ================= mma.sync helpers =================
__device__ __forceinline__ uint32_t smem_u32(const void* p) {
    uint32_t a;
    asm("{ .reg .u64 t; cvta.to.shared.u64 t, %1; cvt.u32.u64 %0, t; }" : "=r"(a) : "l"(p));
    return a;
}
__device__ __forceinline__ void ldsm4(uint32_t* r, uint32_t addr) {
    asm volatile("ldmatrix.sync.aligned.m8n8.x4.shared.b16 {%0,%1,%2,%3}, [%4];"
                 : "=r"(r[0]), "=r"(r[1]), "=r"(r[2]), "=r"(r[3]) : "r"(addr));
}
__device__ __forceinline__ void mma_f16(float* d, const uint32_t* a, const uint32_t* b) {
    asm volatile(
        "mma.sync.aligned.m16n8k16.row.col.f32.f16.f16.f32 "
        "{%0,%1,%2,%3}, {%4,%5,%6,%7}, {%8,%9}, {%0,%1,%2,%3};"
        : "+f"(d[0]), "+f"(d[1]), "+f"(d[2]), "+f"(d[3])
        : "r"(a[0]), "r"(a[1]), "r"(a[2]), "r"(a[3]), "r"(b[0]), "r"(b[1]));
}
__device__ __forceinline__ void cp_async16(uint32_t dst, const void* src) {
    asm volatile("cp.async.cg.shared.global [%0], [%1], 16;" :: "r"(dst), "l"(src));
}
#define CP_COMMIT() asm volatile("cp.async.commit_group;" ::: "memory")
#define CP_WAIT1()  asm volatile("cp.async.wait_group 1;" ::: "memory")
#define CP_WAIT0()  asm volatile("cp.async.wait_group 0;" ::: "memory")
#define SWZ(o) ((o) ^ (((o) >> 3) & 0x70))

// -------- K0: precompute folded vectors, fp16 W1, transposes, constants --------
__global__ void __launch_bounds__(256) k_pre(const float* __restrict__ W1,
                                             const float* __restrict__ b1,
                                             const float* __restrict__ a11,
                                             const float* __restrict__ W2,
                                             const float* __restrict__ b2,
                                             const float* __restrict__ a21,
                                             const float* __restrict__ a22,
                                             const float* __restrict__ Wl) {
    int t = blockIdx.x * 256 + threadIdx.x;   // 0..8191 (32 blocks)
    if (t < F_) {
        float s = 0.f;
        for (int h = 0; h < H1_; ++h) s += a11[h] * W1[h * F_ + t];
        g_wa11f[t] = s;
    }
    if (t < H1_) {
        float s21 = 0.f, s22 = 0.f;
        for (int h2 = 0; h2 < H2_; ++h2) {
            float w = W2[h2 * H1_ + t];
            s21 += a21[h2] * w;
            s22 += a22[h2] * w;
        }
        g_wa21h[t] = s21;
        g_wa22h[t] = s22;
    }
    for (int i = t; i < H1_ * F_; i += 8192)
        g_W1h[i] = __float2half_rn(W1[i]);
    for (int i = t; i < H1_ * H2_; i += 8192) {
        int k = i / H2_, h2 = i % H2_;
        g_W2T[i] = W2[h2 * H1_ + k];
    }
    for (int i = t; i < H2_ * NC_; i += 8192) {
        int h2 = i / NC_, c = i % NC_;
        g_WlT[i] = Wl[c * H2_ + h2];
    }
    if (t == 0) {
        float c11 = 0.f;
        for (int h = 0; h < H1_; ++h) c11 += b1[h] * a11[h];
        float c21 = 0.f, c22 = 0.f;
        for (int h = 0; h < H2_; ++h) { c21 += b2[h] * a21[h]; c22 += b2[h] * a22[h]; }
        g_scalars[0] = c11; g_scalars[1] = c21; g_scalars[2] = c22;
        g_scalars[3] = 0.f; g_scalars[4] = 0.f; g_scalars[5] = 0.f; g_scalars[6] = 0.f;
    }
}

// -------- K1: t1[b] = sign(x[b,:]) . wa11f + c11 --------
__global__ void __launch_bounds__(256) k_t1(const float* __restrict__ x) {
    __shared__ float sred[32];
    int b = blockIdx.x;
    float s = 0.f;
    for (int f = threadIdx.x; f < F_; f += 256)
        s += sgnf(x[(size_t)b * F_ + f]) * g_wa11f[f];
    float tot = blockSumB(s, sred);
    if (threadIdx.x == 0) g_t1[b] = tot + g_scalars[0];
}

// -------- K2: fp16 HMMA GEMM fused with attn1 + layer-1 BN + layer-2 scores --------
// 1024 CTAs x 256 threads (2 CTA/SM); CTA = 1 batch elem: M=64, N=256, K=1024
#define ST_A   0           // 64 x 128B  = 8192
#define ST_B   8192        // 256 x 128B = 32768
#define STAGE  40960       // per-stage bytes; 2 stages = 81920
#define SM_B1   81920      // 256 floats (sD = 64*260*4 = 66560 aliases stages)
#define SM_A12  82944
#define SM_WA22 83968
#define SM_SZ   84992      // 64 floats
#define SM_SRS  85248
#define SM_SRQ  85504
#define SM_SW   85760
#define SM_AB   86016      // ab, bb
#define SM_RED  86048      // 32 floats
#define GEMM_SMEM 86176
#define SD_LD  260         // padded sD row stride (floats)

__global__ void __launch_bounds__(256, 2) k_gemm(const float* __restrict__ nb,
                                                 const float* __restrict__ b1,
                                                 const float* __restrict__ a12,
                                                 const float* __restrict__ g1p,
                                                 const float* __restrict__ be1p) {
    extern __shared__ char dsm[];
    const int tid = threadIdx.x;
    const int lane = tid & 31, wid = tid >> 5;
    const int wm = wid >> 2;          // 0..1  (32-row slab)
    const int wn = wid & 3;           // 0..3  (64-col slab)
    const int b = blockIdx.x;

    const uint32_t sbase = smem_u32(dsm);

    ((float*)(dsm + SM_B1))[tid]   = b1[tid];
    ((float*)(dsm + SM_A12))[tid]  = a12[tid];
    ((float*)(dsm + SM_WA22))[tid] = g_wa22h[tid];

    // ---- per-thread ldmatrix address bases (pre-swizzled; XOR kb later) ----
    uint32_t a_base[2];
    #pragma unroll
    for (int mt = 0; mt < 2; ++mt) {
        uint32_t off = (uint32_t)(((wm << 5) + (mt << 4) + (lane & 15)) * 128 + (lane & 16));
        a_base[mt] = SWZ(off);
    }
    uint32_t b_base[4];
    {
        int nr = (wn << 6) + (lane & 7) + ((lane & 16) >> 1);
        uint32_t off = (uint32_t)(nr * 128 + ((lane & 8) << 1));
        uint32_t s0 = SWZ(off);
        #pragma unroll
        for (int g = 0; g < 4; ++g) b_base[g] = s0 + ((uint32_t)g << 11);
    }

    float acc[2][8][4];
    #pragma unroll
    for (int mt = 0; mt < 2; ++mt)
        #pragma unroll
        for (int nt = 0; nt < 8; ++nt)
            #pragma unroll
            for (int e = 0; e < 4; ++e) acc[mt][nt][e] = 0.f;

    // A-tile loader: 64 rows x 64 cols fp32 -> 16 floats/thread, packed to 8 u32
    const float* Ab = nb + (size_t)b * 64 * F_;
    const int arow = tid >> 2;                 // 0..63
    const int acs  = (tid & 3) << 4;           // 0,16,32,48
    const uint32_t a_st0 = SWZ((uint32_t)(arow * 128 + (acs << 1)));
    const uint32_t a_st1 = SWZ((uint32_t)(arow * 128 + (acs << 1) + 16));

    uint32_t uA[8];
    auto loadA = [&](int c) {
        const float* ap = Ab + (size_t)arow * F_ + c * 64 + acs;
        float4 v0 = *reinterpret_cast<const float4*>(ap);
        float4 v1 = *reinterpret_cast<const float4*>(ap + 4);
        float4 v2 = *reinterpret_cast<const float4*>(ap + 8);
        float4 v3 = *reinterpret_cast<const float4*>(ap + 12);
        uA[0] = pack2(v0.x, v0.y); uA[1] = pack2(v0.z, v0.w);
        uA[2] = pack2(v1.x, v1.y); uA[3] = pack2(v1.z, v1.w);
        uA[4] = pack2(v2.x, v2.y); uA[5] = pack2(v2.z, v2.w);
        uA[6] = pack2(v3.x, v3.y); uA[7] = pack2(v3.z, v3.w);
    };
    auto storeA = [&](int buf) {
        char* st = dsm + buf * STAGE + ST_A;
        *reinterpret_cast<uint4*>(st + a_st0) = make_uint4(uA[0], uA[1], uA[2], uA[3]);
        *reinterpret_cast<uint4*>(st + a_st1) = make_uint4(uA[4], uA[5], uA[6], uA[7]);
    };
    // B-tile loader via cp.async: 2048 16B lines / 256 threads = 8 each
    auto loadB = [&](int c, int buf) {
        const uint32_t stg = sbase + buf * STAGE + ST_B;
        const int k0 = c * 64;
        #pragma unroll
        for (int i = 0; i < 8; ++i) {
            int j = tid + (i << 8);             // 0..2047
            int row = j >> 3, seg = j & 7;
            uint32_t dst = stg + SWZ((uint32_t)(row * 128 + seg * 16));
            const __half* src = g_W1h + (size_t)row * F_ + k0 + seg * 8;
            cp_async16(dst, src);
        }
        CP_COMMIT();
    };

    // ---- prologue: fill both stages ----
    loadA(0); storeA(0); loadB(0, 0);
    loadA(1); storeA(1); loadB(1, 1);
    CP_WAIT1();
    __syncthreads();

    #pragma unroll 1
    for (int c = 0; c < 16; ++c) {
        const int buf = c & 1;
        const uint32_t aS = sbase + buf * STAGE + ST_A;
        const uint32_t bS = sbase + buf * STAGE + ST_B;

        if (c + 2 < 16) loadA(c + 2);   // issue globals before compute

        #pragma unroll
        for (int ks = 0; ks < 4; ++ks) {
            const uint32_t kb = (uint32_t)ks << 5;
            uint32_t ra[2][4];
            ldsm4(ra[0], aS + (a_base[0] ^ kb));
            ldsm4(ra[1], aS + (a_base[1] ^ kb));
            #pragma unroll
            for (int g = 0; g < 4; ++g) {
                uint32_t t4[4];
                ldsm4(t4, bS + (b_base[g] ^ kb));
                mma_f16(acc[0][2*g],   ra[0], &t4[0]);
                mma_f16(acc[0][2*g+1], ra[0], &t4[2]);
                mma_f16(acc[1][2*g],   ra[1], &t4[0]);
                mma_f16(acc[1][2*g+1], ra[1], &t4[2]);
            }
        }
        __syncthreads();                 // done reading stage[buf]
        if (c + 2 < 16) {
            storeA(buf);
            loadB(c + 2, buf);
            CP_WAIT1();
        } else {
            CP_WAIT0();
        }
        __syncthreads();
    }

    // ---------------- fused epilogue (1 batch elem) ----------------
    float* sD = (float*)dsm;                       // [64][SD_LD], aliases stages
    const float* b1s  = (const float*)(dsm + SM_B1);
    const float* a12s = (const float*)(dsm + SM_A12);
    const float* wa22 = (const float*)(dsm + SM_WA22);
    float* sz  = (float*)(dsm + SM_SZ);
    float* srs = (float*)(dsm + SM_SRS);
    float* srq = (float*)(dsm + SM_SRQ);
    float* sW  = (float*)(dsm + SM_SW);
    float* sab = (float*)(dsm + SM_AB);            // [0]=ab, [1]=bb
    float* sred = (float*)(dsm + SM_RED);

    {
        const int g8 = lane >> 2, tq = lane & 3;
        #pragma unroll
        for (int mt = 0; mt < 2; ++mt) {
            int row = (wm << 5) + (mt << 4) + g8;
            #pragma unroll
            for (int nt = 0; nt < 8; ++nt) {
                int col = (wn << 6) + (nt << 3) + (tq << 1);
                sD[row * SD_LD + col]           = acc[mt][nt][0] + b1s[col];
                sD[row * SD_LD + col + 1]       = acc[mt][nt][1] + b1s[col + 1];
                sD[(row + 8) * SD_LD + col]     = acc[mt][nt][2] + b1s[col];
                sD[(row + 8) * SD_LD + col + 1] = acc[mt][nt][3] + b1s[col + 1];
            }
        }
    }
    __syncthreads();

    // pass A: row stats (4 threads per row, 64 rows): BN sums + attn1 scores
    {
        const int r = tid >> 2, ph = tid & 3;
        float rs = 0.f, rq = 0.f, zz = 0.f;
        #pragma unroll 8
        for (int j = 0; j < 64; ++j) {
            int cc = ph + 4 * j;
            float v = sD[r * SD_LD + cc];
            rs += v; rq += v * v; zz += v * a12s[cc];
        }
        rs += __shfl_xor_sync(0xffffffffu, rs, 1); rs += __shfl_xor_sync(0xffffffffu, rs, 2);
        rq += __shfl_xor_sync(0xffffffffu, rq, 1); rq += __shfl_xor_sync(0xffffffffu, rq, 2);
        zz += __shfl_xor_sync(0xffffffffu, zz, 1); zz += __shfl_xor_sync(0xffffffffu, zz, 2);
        if (ph == 0) {
            srs[r] = rs; srq[r] = rq;
            float l = zz + g_t1[b];
            sz[r] = (l > 0.f) ? l : ALPHA_ * l;
        }
    }
    __syncthreads();

    // softmax weights (attn1) + per-b BN coefficients ab, bb
    if (tid < 64) {
        float mx = -1e30f;
        for (int j = 0; j < 64; ++j) mx = fmaxf(mx, sz[j]);
        float den = 0.f;
        for (int j = 0; j < 64; ++j) den += expf(sz[j] - mx);
        sW[tid] = expf(sz[tid] - mx) / den;
        if (tid == 0) {
            float s = 0.f, q = 0.f;
            for (int j = 0; j < 64; ++j) { s += srs[j]; q += srq[j]; }
            const float invb = 1.f / (float)(Nn * H1_);
            float mb = s * invb;
            float vb = q * invb - mb * mb;
            float ab = g1p[0] * rsqrtf(vb + BN_EPS_);
            sab[0] = ab;
            sab[1] = be1p[0] - ab * mb;
        }
    }
    __syncthreads();

    // pass B: layer-2 scores s2[n] = sum_h relu(ab*D+bb) * wa22[h] + c22
    {
        const int r = tid >> 2, ph = tid & 3;
        const float ab = sab[0], bb = sab[1];
        float z2 = 0.f;
        #pragma unroll 8
        for (int j = 0; j < 64; ++j) {
            int cc = ph + 4 * j;
            float v = fmaxf(ab * sD[r * SD_LD + cc] + bb, 0.f);
            z2 += v * wa22[cc];
        }
        z2 += __shfl_xor_sync(0xffffffffu, z2, 1);
        z2 += __shfl_xor_sync(0xffffffffu, z2, 2);
        if (ph == 0)
            g_s2[(size_t)b * Nn + r] = z2 + g_scalars[2];
    }

    // pass C: x1 (raw D x attn1 weights) + write v = relu(ab*D+bb) to global
    {
        const int h = tid;                       // 0..255
        const float ab = sab[0], bb = sab[1];
        float accx = 0.f;
        float* gout = g_v + (size_t)b * (Nn * H1_);
        #pragma unroll 8
        for (int n = 0; n < Nn; ++n) {
            float raw = sD[n * SD_LD + h];
            gout[n * H1_ + h] = fmaxf(ab * raw + bb, 0.f);
            accx += sW[n] * raw;
        }
        g_x1[(size_t)b * H1_ + h] = accx;
        float ts = blockSumB(accx, sred);
        if (tid == 0) atomicAdd(&g_scalars[3], ts);
        float tq2 = blockSumB(accx * accx, sred);
        if (tid == 0) atomicAdd(&g_scalars[4], tq2);
    }
}

// -------- K4: layer-2 softmax + weighted sum (single read of v) --------
__global__ void __launch_bounds__(256) k_attn2(const float* __restrict__ g1p,
                                               const float* __restrict__ be1p) {
    int b = blockIdx.x;
    int h = threadIdx.x;
    __shared__ float sS[Nn];
    __shared__ float sW[Nn];
    __shared__ float sred[32];

    const float invx = 1.f / (float)(B_ * H1_);
    float mxm = g_scalars[3] * invx;
    float vx  = g_scalars[4] * invx - mxm * mxm;
    float ax  = g1p[0] * rsqrtf(vx + BN_EPS_);
    float bx  = be1p[0] - ax * mxm;

    float u = fmaxf(ax * g_x1[b * H1_ + h] + bx, 0.f);
    float t2 = blockSumB(u * g_wa21h[h], sred) + g_scalars[1];

    if (h < Nn) {
        float s = t2 + g_s2[(size_t)b * Nn + h];
        sS[h] = (s > 0.f) ? s : ALPHA_ * s;
    }
    __syncthreads();
    float mx = -1e30f;
    for (int n = 0; n < Nn; ++n) mx = fmaxf(mx, sS[n]);
    float den = 0.f;
    for (int n = 0; n < Nn; ++n) den += expf(sS[n] - mx);
    if (h < Nn) sW[h] = expf(sS[h] - mx) / den;
    __syncthreads();

    const float* base = g_v + (size_t)b * (Nn * H1_);
    float y = 0.f;
    #pragma unroll 8
    for (int n = 0; n < Nn; ++n)
        y += sW[n] * base[n * H1_ + h];
    g_y[b * H1_ + h] = y;
}

// -------- K5: x2 = y @ W2^T + b2 --------
__global__ void __launch_bounds__(128) k_lin2(const float* __restrict__ b2) {
    int bb = blockIdx.x * 8;
    int h2 = threadIdx.x;
    __shared__ float sy[8 * H1_];
    __shared__ float sred[32];
    for (int i = h2; i < 8 * H1_; i += 128) sy[i] = g_y[(size_t)bb * H1_ + i];
    __syncthreads();
    float acc[8];
    #pragma unroll
    for (int i = 0; i < 8; ++i) acc[i] = 0.f;
    for (int k = 0; k < H1_; ++k) {
        float w = g_W2T[k * H2_ + h2];
        #pragma unroll
        for (int i = 0; i < 8; ++i) acc[i] += sy[i * H1_ + k] * w;
    }
    float b2v = b2[h2];
    float ls = 0.f, lq = 0.f;
    #pragma unroll
    for (int i = 0; i < 8; ++i) {
        float s = acc[i] + b2v;
        g_x2[(size_t)(bb + i) * H2_ + h2] = s;
        ls += s; lq += s * s;
    }
    float a = blockSumB(ls, sred);
    if (h2 == 0) atomicAdd(&g_scalars[5], a);
    float q = blockSumB(lq, sred);
    if (h2 == 0) atomicAdd(&g_scalars[6], q);
}

// -------- K6: logits = relu(bn(x2)) @ Wl^T + bl --------
__global__ void __launch_bounds__(128) k_final(const float* __restrict__ g2p,
                                               const float* __restrict__ be2p,
                                               const float* __restrict__ bl,
                                               float* __restrict__ out) {
    int bb = blockIdx.x * 8;
    int c = threadIdx.x;
    const float inv2 = 1.f / (float)(B_ * H2_);
    float m = g_scalars[5] * inv2;
    float v = g_scalars[6] * inv2 - m * m;
    float a2 = g2p[0] * rsqrtf(v + BN_EPS_);
    float s2 = be2p[0] - a2 * m;
    __shared__ float sx[8 * H2_];
    #pragma unroll
    for (int i = 0; i < 8; ++i) {
        float t = a2 * g_x2[(size_t)(bb + i) * H2_ + c] + s2;
        sx[i * H2_ + c] = fmaxf(t, 0.f);
    }
    __syncthreads();
    float acc[8];
    #pragma unroll
    for (int i = 0; i < 8; ++i) acc[i] = 0.f;
    for (int k = 0; k < H2_; ++k) {
        float w = g_WlT[k * NC_ + c];
        #pragma unroll
        for (int i = 0; i < 8; ++i) acc[i] += sx[i * H2_ + k] * w;
    }
    float blc = bl[c];
    #pragma unroll
    for (int i = 0; i < 8; ++i) out[(size_t)(bb + i) * NC_ + c] = acc[i] + blc;
}

extern "C" void kernel_launch(void* const* d_in, const int* in_sizes, int n_in,
                              void* d_out, int out_size) {
    const float* x   = (const float*)d_in[0];
    const float* nb  = (const float*)d_in[1];
    const float* W1  = (const float*)d_in[2];
    const float* b1  = (const float*)d_in[3];
    const float* a11 = (const float*)d_in[4];
    const float* a12 = (const float*)d_in[5];
    const float* g1  = (const float*)d_in[6];
    const float* be1 = (const float*)d_in[7];
    const float* W2  = (const float*)d_in[8];
    const float* b2  = (const float*)d_in[9];
    const float* a21 = (const float*)d_in[10];
    const float* a22 = (const float*)d_in[11];
    const float* g2  = (const float*)d_in[12];
    const float* be2 = (const float*)d_in[13];
    const float* Wl  = (const float*)d_in[14];
    const float* bl  = (const float*)d_in[15];
    float* out = (float*)d_out;

    static int smem_set = 0;
    if (!smem_set) {
        cudaFuncSetAttribute(k_gemm, cudaFuncAttributeMaxDynamicSharedMemorySize, GEMM_SMEM);
        smem_set = 1;
    }

    k_pre<<<32, 256>>>(W1, b1, a11, W2, b2, a21, a22, Wl);
    k_t1<<<B_, 256>>>(x);
    k_gemm<<<B_, 256, GEMM_SMEM>>>(nb, b1, a12, g1, be1);
    k_attn2<<<B_, 256>>>(g1, be1);
    k_lin2<<<B_ / 8, 128>>>(b2);
    k_final<<<B_ / 8, 128>>>(g2, be2, bl, out);
}

// round 16
// speedup vs baseline: 3.9962x; 1.0011x over previous
#include <cuda_runtime.h>
#include <cuda_fp16.h>
#include <cstdint>

// Shapes (fixed by the problem)
#define B_  1024
#define Nn  64
#define F_  1024
#define H1_ 256
#define H2_ 128
#define NC_ 128
#define R_  65536          // B_*Nn
#define ALPHA_ 0.2f
#define BN_EPS_ 1e-5f

// -------- scratch (static __device__ arrays; no allocation) --------
__device__ float g_v[R_ * H1_];        // 64 MB: relu(bn(nbh1)) per-neighbor features
__device__ float g_x1[B_ * H1_];       // layer-1 output x (pre-BN)
__device__ float g_y[B_ * H1_];        // attention-weighted BN'd neighbors (layer 2)
__device__ float g_x2[B_ * H2_];       // layer-2 output x (pre-BN)
__device__ float g_t1[B_];             // self attention score part, layer 1
__device__ float g_s2[B_ * Nn];        // layer-2 neighbor scores (pre-t2)
__device__ float g_wa11f[F_];          // W1^T @ a11
__device__ float g_wa21h[H1_];         // W2^T @ a21
__device__ float g_wa22h[H1_];         // W2^T @ a22
__device__ float g_W2T[H1_ * H2_];     // W2 transposed [h1][h2]
__device__ float g_WlT[H2_ * NC_];     // Wl transposed [h2][c]
__device__ float g_scalars[8];         // 0:c11 1:c21 2:c22 3:xsum 4:xsq 5:x2sum 6:x2sq
__device__ __half g_W1h[H1_ * F_];     // fp16 W1

__device__ __forceinline__ float sgnf(float v) {
    return (v > 0.f) ? 1.f : ((v < 0.f) ? -1.f : 0.f);
}
// branchless: +-1.0h carrying the fp32 sign bit (inputs are continuous -> no exact zeros)
__device__ __forceinline__ uint32_t pack2(float x, float y) {
    uint32_t xb = __float_as_uint(x), yb = __float_as_uint(y);
    return 0x3C003C00u | ((xb >> 16) & 0x8000u) | (yb & 0x80000000u);
}

// block-wide sum with broadcast; sred must hold >= 32 floats; result in sred[16]
__device__ __forceinline__ float blockSumB(float v, float* sred) {
    const unsigned FULL = 0xffffffffu;
    #pragma unroll
    for (int o = 16; o; o >>= 1) v += __shfl_xor_sync(FULL, v, o);
    int lane = threadIdx.x & 31, wid = threadIdx.x >> 5;
    __syncthreads();
    if (lane == 0) sred[wid] = v;
    __syncthreads();
    if (wid == 0) {
        float t = (lane * 32 < (int)blockDim.x) ? sred[lane] : 0.f;
        #pragma unroll
        for (int o = 16; o; o >>= 1) t += __shfl_xor_sync(FULL, t, o);
        if (lane == 0) sred[16] = t;
    }
    __syncthreads();
    return sred[16];
}

// ================= mma.sync helpers =================
__device__ __forceinline__ uint32_t smem_u32(const void* p) {
    uint32_t a;
    asm("{ .reg .u64 t; cvta.to.shared.u64 t, %1; cvt.u32.u64 %0, t; }" : "=r"(a) : "l"(p));
    return a;
}
__device__ __forceinline__ void ldsm4(uint32_t* r, uint32_t addr) {
    asm volatile("ldmatrix.sync.aligned.m8n8.x4.shared.b16 {%0,%1,%2,%3}, [%4];"
                 : "=r"(r[0]), "=r"(r[1]), "=r"(r[2]), "=r"(r[3]) : "r"(addr));
}
__device__ __forceinline__ void mma_f16(float* d, const uint32_t* a, const uint32_t* b) {
    asm volatile(
        "mma.sync.aligned.m16n8k16.row.col.f32.f16.f16.f32 "
        "{%0,%1,%2,%3}, {%4,%5,%6,%7}, {%8,%9}, {%0,%1,%2,%3};"
        : "+f"(d[0]), "+f"(d[1]), "+f"(d[2]), "+f"(d[3])
        : "r"(a[0]), "r"(a[1]), "r"(a[2]), "r"(a[3]), "r"(b[0]), "r"(b[1]));
}
__device__ __forceinline__ void cp_async16(uint32_t dst, const void* src) {
    asm volatile("cp.async.cg.shared.global [%0], [%1], 16;" :: "r"(dst), "l"(src));
}
#define CP_COMMIT() asm volatile("cp.async.commit_group;" ::: "memory")
#define CP_WAIT1()  asm volatile("cp.async.wait_group 1;" ::: "memory")
#define CP_WAIT0()  asm volatile("cp.async.wait_group 0;" ::: "memory")
#define SWZ(o) ((o) ^ (((o) >> 3) & 0x70))

// -------- K0: precompute folded vectors, fp16 W1, transposes, constants --------
__global__ void __launch_bounds__(256) k_pre(const float* __restrict__ W1,
                                             const float* __restrict__ b1,
                                             const float* __restrict__ a11,
                                             const float* __restrict__ W2,
                                             const float* __restrict__ b2,
                                             const float* __restrict__ a21,
                                             const float* __restrict__ a22,
                                             const float* __restrict__ Wl) {
    int t = blockIdx.x * 256 + threadIdx.x;   // 0..8191 (32 blocks)
    if (t < F_) {
        float s = 0.f;
        for (int h = 0; h < H1_; ++h) s += a11[h] * W1[h * F_ + t];
        g_wa11f[t] = s;
    }
    if (t < H1_) {
        float s21 = 0.f, s22 = 0.f;
        for (int h2 = 0; h2 < H2_; ++h2) {
            float w = W2[h2 * H1_ + t];
            s21 += a21[h2] * w;
            s22 += a22[h2] * w;
        }
        g_wa21h[t] = s21;
        g_wa22h[t] = s22;
    }
    for (int i = t; i < H1_ * F_; i += 8192)
        g_W1h[i] = __float2half_rn(W1[i]);
    for (int i = t; i < H1_ * H2_; i += 8192) {
        int k = i / H2_, h2 = i % H2_;
        g_W2T[i] = W2[h2 * H1_ + k];
    }
    for (int i = t; i < H2_ * NC_; i += 8192) {
        int h2 = i / NC_, c = i % NC_;
        g_WlT[i] = Wl[c * H2_ + h2];
    }
    if (t == 0) {
        float c11 = 0.f;
        for (int h = 0; h < H1_; ++h) c11 += b1[h] * a11[h];
        float c21 = 0.f, c22 = 0.f;
        for (int h = 0; h < H2_; ++h) { c21 += b2[h] * a21[h]; c22 += b2[h] * a22[h]; }
        g_scalars[0] = c11; g_scalars[1] = c21; g_scalars[2] = c22;
        g_scalars[3] = 0.f; g_scalars[4] = 0.f; g_scalars[5] = 0.f; g_scalars[6] = 0.f;
    }
}

// -------- K1: t1[b] = sign(x[b,:]) . wa11f + c11 --------
__global__ void __launch_bounds__(256) k_t1(const float* __restrict__ x) {
    __shared__ float sred[32];
    int b = blockIdx.x;
    float s = 0.f;
    for (int f = threadIdx.x; f < F_; f += 256)
        s += sgnf(x[(size_t)b * F_ + f]) * g_wa11f[f];
    float tot = blockSumB(s, sred);
    if (threadIdx.x == 0) g_t1[b] = tot + g_scalars[0];
}

// -------- K2: fp16 HMMA GEMM fused with attn1 + layer-1 BN + layer-2 scores --------
// 1024 CTAs x 256 threads (2 CTA/SM); CTA = 1 batch elem: M=64, N=256, K=1024
#define ST_A   0           // 64 x 128B  = 8192
#define ST_B   8192        // 256 x 128B = 32768
#define STAGE  40960       // per-stage bytes; 2 stages = 81920
#define SM_B1   81920      // 256 floats (sD = 64*260*4 = 66560 aliases stages)
#define SM_A12  82944
#define SM_WA22 83968
#define SM_SZ   84992      // 64 floats
#define SM_SRS  85248
#define SM_SRQ  85504
#define SM_SW   85760
#define SM_AB   86016      // ab, bb
#define SM_RED  86048      // 32 floats
#define GEMM_SMEM 86176
#define SD_LD  260         // padded sD row stride (floats)

__global__ void __launch_bounds__(256, 2) k_gemm(const float* __restrict__ nb,
                                                 const float* __restrict__ b1,
                                                 const float* __restrict__ a12,
                                                 const float* __restrict__ g1p,
                                                 const float* __restrict__ be1p) {
    extern __shared__ char dsm[];
    const int tid = threadIdx.x;
    const int lane = tid & 31, wid = tid >> 5;
    const int wm = wid >> 2;          // 0..1  (32-row slab)
    const int wn = wid & 3;           // 0..3  (64-col slab)
    const int b = blockIdx.x;

    const uint32_t sbase = smem_u32(dsm);

    ((float*)(dsm + SM_B1))[tid]   = b1[tid];
    ((float*)(dsm + SM_A12))[tid]  = a12[tid];
    ((float*)(dsm + SM_WA22))[tid] = g_wa22h[tid];

    // ---- per-thread ldmatrix address bases (pre-swizzled; XOR kb later) ----
    uint32_t a_base[2];
    #pragma unroll
    for (int mt = 0; mt < 2; ++mt) {
        uint32_t off = (uint32_t)(((wm << 5) + (mt << 4) + (lane & 15)) * 128 + (lane & 16));
        a_base[mt] = SWZ(off);
    }
    uint32_t b_base[4];
    {
        int nr = (wn << 6) + (lane & 7) + ((lane & 16) >> 1);
        uint32_t off = (uint32_t)(nr * 128 + ((lane & 8) << 1));
        uint32_t s0 = SWZ(off);
        #pragma unroll
        for (int g = 0; g < 4; ++g) b_base[g] = s0 + ((uint32_t)g << 11);
    }

    float acc[2][8][4];
    #pragma unroll
    for (int mt = 0; mt < 2; ++mt)
        #pragma unroll
        for (int nt = 0; nt < 8; ++nt)
            #pragma unroll
            for (int e = 0; e < 4; ++e) acc[mt][nt][e] = 0.f;

    // A-tile loader: 64 rows x 64 cols fp32 -> 16 floats/thread, packed to 8 u32
    const float* Ab = nb + (size_t)b * 64 * F_;
    const int arow = tid >> 2;                 // 0..63
    const int acs  = (tid & 3) << 4;           // 0,16,32,48
    const uint32_t a_st0 = SWZ((uint32_t)(arow * 128 + (acs << 1)));
    const uint32_t a_st1 = SWZ((uint32_t)(arow * 128 + (acs << 1) + 16));

    uint32_t uA[8];
    auto loadA = [&](int c) {
        const float* ap = Ab + (size_t)arow * F_ + c * 64 + acs;
        float4 v0 = *reinterpret_cast<const float4*>(ap);
        float4 v1 = *reinterpret_cast<const float4*>(ap + 4);
        float4 v2 = *reinterpret_cast<const float4*>(ap + 8);
        float4 v3 = *reinterpret_cast<const float4*>(ap + 12);
        uA[0] = pack2(v0.x, v0.y); uA[1] = pack2(v0.z, v0.w);
        uA[2] = pack2(v1.x, v1.y); uA[3] = pack2(v1.z, v1.w);
        uA[4] = pack2(v2.x, v2.y); uA[5] = pack2(v2.z, v2.w);
        uA[6] = pack2(v3.x, v3.y); uA[7] = pack2(v3.z, v3.w);
    };
    auto storeA = [&](int buf) {
        char* st = dsm + buf * STAGE + ST_A;
        *reinterpret_cast<uint4*>(st + a_st0) = make_uint4(uA[0], uA[1], uA[2], uA[3]);
        *reinterpret_cast<uint4*>(st + a_st1) = make_uint4(uA[4], uA[5], uA[6], uA[7]);
    };
    // B-tile loader via cp.async: 2048 16B lines / 256 threads = 8 each
    auto loadB = [&](int c, int buf) {
        const uint32_t stg = sbase + buf * STAGE + ST_B;
        const int k0 = c * 64;
        #pragma unroll
        for (int i = 0; i < 8; ++i) {
            int j = tid + (i << 8);             // 0..2047
            int row = j >> 3, seg = j & 7;
            uint32_t dst = stg + SWZ((uint32_t)(row * 128 + seg * 16));
            const __half* src = g_W1h + (size_t)row * F_ + k0 + seg * 8;
            cp_async16(dst, src);
        }
        CP_COMMIT();
    };

    // ---- prologue: fill both stages ----
    loadA(0); storeA(0); loadB(0, 0);
    loadA(1); storeA(1); loadB(1, 1);
    CP_WAIT1();
    __syncthreads();

    #pragma unroll 1
    for (int c = 0; c < 16; ++c) {
        const int buf = c & 1;
        const uint32_t aS = sbase + buf * STAGE + ST_A;
        const uint32_t bS = sbase + buf * STAGE + ST_B;

        if (c + 2 < 16) loadA(c + 2);   // issue globals before compute

        #pragma unroll
        for (int ks = 0; ks < 4; ++ks) {
            const uint32_t kb = (uint32_t)ks << 5;
            uint32_t ra[2][4];
            ldsm4(ra[0], aS + (a_base[0] ^ kb));
            ldsm4(ra[1], aS + (a_base[1] ^ kb));
            #pragma unroll
            for (int g = 0; g < 4; ++g) {
                uint32_t t4[4];
                ldsm4(t4, bS + (b_base[g] ^ kb));
                mma_f16(acc[0][2*g],   ra[0], &t4[0]);
                mma_f16(acc[0][2*g+1], ra[0], &t4[2]);
                mma_f16(acc[1][2*g],   ra[1], &t4[0]);
                mma_f16(acc[1][2*g+1], ra[1], &t4[2]);
            }
        }
        __syncthreads();                 // done reading stage[buf]
        if (c + 2 < 16) {
            storeA(buf);
            loadB(c + 2, buf);
            CP_WAIT1();
        } else {
            CP_WAIT0();
        }
        __syncthreads();
    }

    // ---------------- fused epilogue (1 batch elem) ----------------
    float* sD = (float*)dsm;                       // [64][SD_LD], aliases stages
    const float* b1s  = (const float*)(dsm + SM_B1);
    const float* a12s = (const float*)(dsm + SM_A12);
    const float* wa22 = (const float*)(dsm + SM_WA22);
    float* sz  = (float*)(dsm + SM_SZ);
    float* srs = (float*)(dsm + SM_SRS);
    float* srq = (float*)(dsm + SM_SRQ);
    float* sW  = (float*)(dsm + SM_SW);
    float* sab = (float*)(dsm + SM_AB);            // [0]=ab, [1]=bb
    float* sred = (float*)(dsm + SM_RED);

    {
        const int g8 = lane >> 2, tq = lane & 3;
        #pragma unroll
        for (int mt = 0; mt < 2; ++mt) {
            int row = (wm << 5) + (mt << 4) + g8;
            #pragma unroll
            for (int nt = 0; nt < 8; ++nt) {
                int col = (wn << 6) + (nt << 3) + (tq << 1);
                sD[row * SD_LD + col]           = acc[mt][nt][0] + b1s[col];
                sD[row * SD_LD + col + 1]       = acc[mt][nt][1] + b1s[col + 1];
                sD[(row + 8) * SD_LD + col]     = acc[mt][nt][2] + b1s[col];
                sD[(row + 8) * SD_LD + col + 1] = acc[mt][nt][3] + b1s[col + 1];
            }
        }
    }
    __syncthreads();

    // pass A: row stats (4 threads per row, 64 rows): BN sums + attn1 scores
    {
        const int r = tid >> 2, ph = tid & 3;
        float rs = 0.f, rq = 0.f, zz = 0.f;
        #pragma unroll 8
        for (int j = 0; j < 64; ++j) {
            int cc = ph + 4 * j;
            float v = sD[r * SD_LD + cc];
            rs += v; rq += v * v; zz += v * a12s[cc];
        }
        rs += __shfl_xor_sync(0xffffffffu, rs, 1); rs += __shfl_xor_sync(0xffffffffu, rs, 2);
        rq += __shfl_xor_sync(0xffffffffu, rq, 1); rq += __shfl_xor_sync(0xffffffffu, rq, 2);
        zz += __shfl_xor_sync(0xffffffffu, zz, 1); zz += __shfl_xor_sync(0xffffffffu, zz, 2);
        if (ph == 0) {
            srs[r] = rs; srq[r] = rq;
            float l = zz + g_t1[b];
            sz[r] = (l > 0.f) ? l : ALPHA_ * l;
        }
    }
    __syncthreads();

    // softmax weights (attn1) + per-b BN coefficients ab, bb
    if (tid < 64) {
        float mx = -1e30f;
        for (int j = 0; j < 64; ++j) mx = fmaxf(mx, sz[j]);
        float den = 0.f;
        for (int j = 0; j < 64; ++j) den += expf(sz[j] - mx);
        sW[tid] = expf(sz[tid] - mx) / den;
        if (tid == 0) {
            float s = 0.f, q = 0.f;
            for (int j = 0; j < 64; ++j) { s += srs[j]; q += srq[j]; }
            const float invb = 1.f / (float)(Nn * H1_);
            float mb = s * invb;
            float vb = q * invb - mb * mb;
            float ab = g1p[0] * rsqrtf(vb + BN_EPS_);
            sab[0] = ab;
            sab[1] = be1p[0] - ab * mb;
        }
    }
    __syncthreads();

    // pass B: layer-2 scores s2[n] = sum_h relu(ab*D+bb) * wa22[h] + c22
    {
        const int r = tid >> 2, ph = tid & 3;
        const float ab = sab[0], bb = sab[1];
        float z2 = 0.f;
        #pragma unroll 8
        for (int j = 0; j < 64; ++j) {
            int cc = ph + 4 * j;
            float v = fmaxf(ab * sD[r * SD_LD + cc] + bb, 0.f);
            z2 += v * wa22[cc];
        }
        z2 += __shfl_xor_sync(0xffffffffu, z2, 1);
        z2 += __shfl_xor_sync(0xffffffffu, z2, 2);
        if (ph == 0)
            g_s2[(size_t)b * Nn + r] = z2 + g_scalars[2];
    }

    // pass C: x1 (raw D x attn1 weights) + write v = relu(ab*D+bb) to global
    {
        const int h = tid;                       // 0..255
        const float ab = sab[0], bb = sab[1];
        float accx = 0.f;
        float* gout = g_v + (size_t)b * (Nn * H1_);
        #pragma unroll 8
        for (int n = 0; n < Nn; ++n) {
            float raw = sD[n * SD_LD + h];
            gout[n * H1_ + h] = fmaxf(ab * raw + bb, 0.f);
            accx += sW[n] * raw;
        }
        g_x1[(size_t)b * H1_ + h] = accx;
        float ts = blockSumB(accx, sred);
        if (tid == 0) atomicAdd(&g_scalars[3], ts);
        float tq2 = blockSumB(accx * accx, sred);
        if (tid == 0) atomicAdd(&g_scalars[4], tq2);
    }
}

// -------- K4: layer-2 softmax + weighted sum (single read of v) --------
__global__ void __launch_bounds__(256) k_attn2(const float* __restrict__ g1p,
                                               const float* __restrict__ be1p) {
    int b = blockIdx.x;
    int h = threadIdx.x;
    __shared__ float sS[Nn];
    __shared__ float sW[Nn];
    __shared__ float sred[32];

    const float invx = 1.f / (float)(B_ * H1_);
    float mxm = g_scalars[3] * invx;
    float vx  = g_scalars[4] * invx - mxm * mxm;
    float ax  = g1p[0] * rsqrtf(vx + BN_EPS_);
    float bx  = be1p[0] - ax * mxm;

    float u = fmaxf(ax * g_x1[b * H1_ + h] + bx, 0.f);
    float t2 = blockSumB(u * g_wa21h[h], sred) + g_scalars[1];

    if (h < Nn) {
        float s = t2 + g_s2[(size_t)b * Nn + h];
        sS[h] = (s > 0.f) ? s : ALPHA_ * s;
    }
    __syncthreads();
    float mx = -1e30f;
    for (int n = 0; n < Nn; ++n) mx = fmaxf(mx, sS[n]);
    float den = 0.f;
    for (int n = 0; n < Nn; ++n) den += expf(sS[n] - mx);
    if (h < Nn) sW[h] = expf(sS[h] - mx) / den;
    __syncthreads();

    const float* base = g_v + (size_t)b * (Nn * H1_);
    float y = 0.f;
    #pragma unroll 8
    for (int n = 0; n < Nn; ++n)
        y += sW[n] * base[n * H1_ + h];
    g_y[b * H1_ + h] = y;
}

// -------- K5: x2 = y @ W2^T + b2 --------
__global__ void __launch_bounds__(128) k_lin2(const float* __restrict__ b2) {
    int bb = blockIdx.x * 8;
    int h2 = threadIdx.x;
    __shared__ float sy[8 * H1_];
    __shared__ float sred[32];
    for (int i = h2; i < 8 * H1_; i += 128) sy[i] = g_y[(size_t)bb * H1_ + i];
    __syncthreads();
    float acc[8];
    #pragma unroll
    for (int i = 0; i < 8; ++i) acc[i] = 0.f;
    for (int k = 0; k < H1_; ++k) {
        float w = g_W2T[k * H2_ + h2];
        #pragma unroll
        for (int i = 0; i < 8; ++i) acc[i] += sy[i * H1_ + k] * w;
    }
    float b2v = b2[h2];
    float ls = 0.f, lq = 0.f;
    #pragma unroll
    for (int i = 0; i < 8; ++i) {
        float s = acc[i] + b2v;
        g_x2[(size_t)(bb + i) * H2_ + h2] = s;
        ls += s; lq += s * s;
    }
    float a = blockSumB(ls, sred);
    if (h2 == 0) atomicAdd(&g_scalars[5], a);
    float q = blockSumB(lq, sred);
    if (h2 == 0) atomicAdd(&g_scalars[6], q);
}

// -------- K6: logits = relu(bn(x2)) @ Wl^T + bl --------
__global__ void __launch_bounds__(128) k_final(const float* __restrict__ g2p,
                                               const float* __restrict__ be2p,
                                               const float* __restrict__ bl,
                                               float* __restrict__ out) {
    int bb = blockIdx.x * 8;
    int c = threadIdx.x;
    const float inv2 = 1.f / (float)(B_ * H2_);
    float m = g_scalars[5] * inv2;
    float v = g_scalars[6] * inv2 - m * m;
    float a2 = g2p[0] * rsqrtf(v + BN_EPS_);
    float s2 = be2p[0] - a2 * m;
    __shared__ float sx[8 * H2_];
    #pragma unroll
    for (int i = 0; i < 8; ++i) {
        float t = a2 * g_x2[(size_t)(bb + i) * H2_ + c] + s2;
        sx[i * H2_ + c] = fmaxf(t, 0.f);
    }
    __syncthreads();
    float acc[8];
    #pragma unroll
    for (int i = 0; i < 8; ++i) acc[i] = 0.f;
    for (int k = 0; k < H2_; ++k) {
        float w = g_WlT[k * NC_ + c];
        #pragma unroll
        for (int i = 0; i < 8; ++i) acc[i] += sx[i * H2_ + k] * w;
    }
    float blc = bl[c];
    #pragma unroll
    for (int i = 0; i < 8; ++i) out[(size_t)(bb + i) * NC_ + c] = acc[i] + blc;
}

extern "C" void kernel_launch(void* const* d_in, const int* in_sizes, int n_in,
                              void* d_out, int out_size) {
    const float* x   = (const float*)d_in[0];
    const float* nb  = (const float*)d_in[1];
    const float* W1  = (const float*)d_in[2];
    const float* b1  = (const float*)d_in[3];
    const float* a11 = (const float*)d_in[4];
    const float* a12 = (const float*)d_in[5];
    const float* g1  = (const float*)d_in[6];
    const float* be1 = (const float*)d_in[7];
    const float* W2  = (const float*)d_in[8];
    const float* b2  = (const float*)d_in[9];
    const float* a21 = (const float*)d_in[10];
    const float* a22 = (const float*)d_in[11];
    const float* g2  = (const float*)d_in[12];
    const float* be2 = (const float*)d_in[13];
    const float* Wl  = (const float*)d_in[14];
    const float* bl  = (const float*)d_in[15];
    float* out = (float*)d_out;

    static int smem_set = 0;
    if (!smem_set) {
        cudaFuncSetAttribute(k_gemm, cudaFuncAttributeMaxDynamicSharedMemorySize, GEMM_SMEM);
        smem_set = 1;
    }

    k_pre<<<32, 256>>>(W1, b1, a11, W2, b2, a21, a22, Wl);
    k_t1<<<B_, 256>>>(x);
    k_gemm<<<B_, 256, GEMM_SMEM>>>(nb, b1, a12, g1, be1);
    k_attn2<<<B_, 256>>>(g1, be1);
    k_lin2<<<B_ / 8, 128>>>(b2);
    k_final<<<B_ / 8, 128>>>(g2, be2, bl, out);
}

// round 17
// speedup vs baseline: 4.0328x; 1.0092x over previous
#include <cuda_runtime.h>
#include <cuda_fp16.h>
#include <cstdint>

// Shapes (fixed by the problem)
#define B_  1024
#define Nn  64
#define F_  1024
#define H1_ 256
#define H2_ 128
#define NC_ 128
#define R_  65536          // B_*Nn
#define ALPHA_ 0.2f
#define BN_EPS_ 1e-5f

// -------- scratch (static __device__ arrays; no allocation) --------
__device__ float g_v[R_ * H1_];        // 64 MB: relu(bn(nbh1)) per-neighbor features
__device__ float g_x1[B_ * H1_];       // layer-1 output x (pre-BN)
__device__ float g_y[B_ * H1_];        // attention-weighted BN'd neighbors (layer 2)
__device__ float g_x2[B_ * H2_];       // layer-2 output x (pre-BN)
__device__ float g_t1[B_];             // self attention score part, layer 1
__device__ float g_s2[B_ * Nn];        // layer-2 neighbor scores (pre-t2)
__device__ float g_wa11f[F_];          // W1^T @ a11
__device__ float g_wa21h[H1_];         // W2^T @ a21
__device__ float g_wa22h[H1_];         // W2^T @ a22
__device__ float g_W2T[H1_ * H2_];     // W2 transposed [h1][h2]
__device__ float g_WlT[H2_ * NC_];     // Wl transposed [h2][c]
__device__ float g_scalars[8];         // 0:c11 1:c21 2:c22 3:xsum 4:xsq 5:x2sum 6:x2sq
__device__ __half g_W1h[H1_ * F_];     // fp16 W1

__device__ __forceinline__ float sgnf(float v) {
    return (v > 0.f) ? 1.f : ((v < 0.f) ? -1.f : 0.f);
}
// branchless: +-1.0h carrying the fp32 sign bit (inputs are continuous -> no exact zeros)
__device__ __forceinline__ uint32_t pack2(float x, float y) {
    uint32_t xb = __float_as_uint(x), yb = __float_as_uint(y);
    return 0x3C003C00u | ((xb >> 16) & 0x8000u) | (yb & 0x80000000u);
}

// block-wide sum with broadcast; sred must hold >= 32 floats; result in sred[16]
__device__ __forceinline__ float blockSumB(float v, float* sred) {
    const unsigned FULL = 0xffffffffu;
    #pragma unroll
    for (int o = 16; o; o >>= 1) v += __shfl_xor_sync(FULL, v, o);
    int lane = threadIdx.x & 31, wid = threadIdx.x >> 5;
    __syncthreads();
    if (lane == 0) sred[wid] = v;
    __syncthreads();
    if (wid == 0) {
        float t = (lane * 32 < (int)blockDim.x) ? sred[lane] : 0.f;
        #pragma unroll
        for (int o = 16; o; o >>= 1) t += __shfl_xor_sync(FULL, t, o);
        if (lane == 0) sred[16] = t;
    }
    __syncthreads();
    return sred[16];
}

// ================= mma.sync helpers =================
__device__ __forceinline__ uint32_t smem_u32(const void* p) {
    uint32_t a;
    asm("{ .reg .u64 t; cvta.to.shared.u64 t, %1; cvt.u32.u64 %0, t; }" : "=r"(a) : "l"(p));
    return a;
}
__device__ __forceinline__ void ldsm4(uint32_t* r, uint32_t addr) {
    asm volatile("ldmatrix.sync.aligned.m8n8.x4.shared.b16 {%0,%1,%2,%3}, [%4];"
                 : "=r"(r[0]), "=r"(r[1]), "=r"(r[2]), "=r"(r[3]) : "r"(addr));
}
__device__ __forceinline__ void mma_f16(float* d, const uint32_t* a, const uint32_t* b) {
    asm volatile(
        "mma.sync.aligned.m16n8k16.row.col.f32.f16.f16.f32 "
        "{%0,%1,%2,%3}, {%4,%5,%6,%7}, {%8,%9}, {%0,%1,%2,%3};"
        : "+f"(d[0]), "+f"(d[1]), "+f"(d[2]), "+f"(d[3])
        : "r"(a[0]), "r"(a[1]), "r"(a[2]), "r"(a[3]), "r"(b[0]), "r"(b[1]));
}
__device__ __forceinline__ void cp_async16(uint32_t dst, const void* src) {
    asm volatile("cp.async.cg.shared.global [%0], [%1], 16;" :: "r"(dst), "l"(src));
}
#define CP_COMMIT() asm volatile("cp.async.commit_group;" ::: "memory")
#define CP_WAIT1()  asm volatile("cp.async.wait_group 1;" ::: "memory")
#define CP_WAIT0()  asm volatile("cp.async.wait_group 0;" ::: "memory")
#define SWZ(o) ((o) ^ (((o) >> 3) & 0x70))

// -------- K0: precompute folded vectors, fp16 W1, transposes, constants --------
__global__ void __launch_bounds__(256) k_pre(const float* __restrict__ W1,
                                             const float* __restrict__ b1,
                                             const float* __restrict__ a11,
                                             const float* __restrict__ W2,
                                             const float* __restrict__ b2,
                                             const float* __restrict__ a21,
                                             const float* __restrict__ a22,
                                             const float* __restrict__ Wl) {
    int t = blockIdx.x * 256 + threadIdx.x;   // 0..8191 (32 blocks)
    if (t < F_) {
        float s = 0.f;
        for (int h = 0; h < H1_; ++h) s += a11[h] * W1[h * F_ + t];
        g_wa11f[t] = s;
    }
    if (t < H1_) {
        float s21 = 0.f, s22 = 0.f;
        for (int h2 = 0; h2 < H2_; ++h2) {
            float w = W2[h2 * H1_ + t];
            s21 += a21[h2] * w;
            s22 += a22[h2] * w;
        }
        g_wa21h[t] = s21;
        g_wa22h[t] = s22;
    }
    for (int i = t; i < H1_ * F_; i += 8192)
        g_W1h[i] = __float2half_rn(W1[i]);
    for (int i = t; i < H1_ * H2_; i += 8192) {
        int k = i / H2_, h2 = i % H2_;
        g_W2T[i] = W2[h2 * H1_ + k];
    }
    for (int i = t; i < H2_ * NC_; i += 8192) {
        int h2 = i / NC_, c = i % NC_;
        g_WlT[i] = Wl[c * H2_ + h2];
    }
    if (t == 0) {
        float c11 = 0.f;
        for (int h = 0; h < H1_; ++h) c11 += b1[h] * a11[h];
        float c21 = 0.f, c22 = 0.f;
        for (int h = 0; h < H2_; ++h) { c21 += b2[h] * a21[h]; c22 += b2[h] * a22[h]; }
        g_scalars[0] = c11; g_scalars[1] = c21; g_scalars[2] = c22;
        g_scalars[3] = 0.f; g_scalars[4] = 0.f; g_scalars[5] = 0.f; g_scalars[6] = 0.f;
    }
}

// -------- K1: t1[b] = sign(x[b,:]) . wa11f + c11 --------
__global__ void __launch_bounds__(256) k_t1(const float* __restrict__ x) {
    __shared__ float sred[32];
    int b = blockIdx.x;
    float s = 0.f;
    for (int f = threadIdx.x; f < F_; f += 256)
        s += sgnf(x[(size_t)b * F_ + f]) * g_wa11f[f];
    float tot = blockSumB(s, sred);
    if (threadIdx.x == 0) g_t1[b] = tot + g_scalars[0];
}

// -------- K2: fp16 HMMA GEMM fused with attn1 + layer-1 BN + layer-2 scores --------
// 1024 CTAs x 256 threads (2 CTA/SM); CTA = 1 batch elem: M=64, N=256, K=1024
#define ST_A   0           // 64 x 128B  = 8192
#define ST_B   8192        // 256 x 128B = 32768
#define STAGE  40960       // per-stage bytes; 2 stages = 81920
#define SM_B1   81920      // 256 floats (sD = 64*260*4 = 66560 aliases stages)
#define SM_A12  82944
#define SM_WA22 83968
#define SM_SZ   84992      // 64 floats
#define SM_SRS  85248
#define SM_SRQ  85504
#define SM_SW   85760
#define SM_AB   86016      // ab, bb
#define SM_RED  86048      // 32 floats
#define GEMM_SMEM 86176
#define SD_LD  260         // padded sD row stride (floats)

__global__ void __launch_bounds__(256, 2) k_gemm(const float* __restrict__ nb,
                                                 const float* __restrict__ b1,
                                                 const float* __restrict__ a12,
                                                 const float* __restrict__ g1p,
                                                 const float* __restrict__ be1p) {
    extern __shared__ char dsm[];
    const int tid = threadIdx.x;
    const int lane = tid & 31, wid = tid >> 5;
    const int wm = wid >> 2;          // 0..1  (32-row slab)
    const int wn = wid & 3;           // 0..3  (64-col slab)
    const int b = blockIdx.x;

    const uint32_t sbase = smem_u32(dsm);

    ((float*)(dsm + SM_B1))[tid]   = b1[tid];
    ((float*)(dsm + SM_A12))[tid]  = a12[tid];
    ((float*)(dsm + SM_WA22))[tid] = g_wa22h[tid];

    // ---- per-thread ldmatrix address bases (pre-swizzled; XOR kb later) ----
    uint32_t a_base[2];
    #pragma unroll
    for (int mt = 0; mt < 2; ++mt) {
        uint32_t off = (uint32_t)(((wm << 5) + (mt << 4) + (lane & 15)) * 128 + (lane & 16));
        a_base[mt] = SWZ(off);
    }
    uint32_t b_base[4];
    {
        int nr = (wn << 6) + (lane & 7) + ((lane & 16) >> 1);
        uint32_t off = (uint32_t)(nr * 128 + ((lane & 8) << 1));
        uint32_t s0 = SWZ(off);
        #pragma unroll
        for (int g = 0; g < 4; ++g) b_base[g] = s0 + ((uint32_t)g << 11);
    }

    float acc[2][8][4];
    #pragma unroll
    for (int mt = 0; mt < 2; ++mt)
        #pragma unroll
        for (int nt = 0; nt < 8; ++nt)
            #pragma unroll
            for (int e = 0; e < 4; ++e) acc[mt][nt][e] = 0.f;

    // A-tile loader: 64 rows x 64 cols fp32 -> 16 floats/thread, packed to 8 u32
    const float* Ab = nb + (size_t)b * 64 * F_;
    const int arow = tid >> 2;                 // 0..63
    const int acs  = (tid & 3) << 4;           // 0,16,32,48
    const uint32_t a_st0 = SWZ((uint32_t)(arow * 128 + (acs << 1)));
    const uint32_t a_st1 = SWZ((uint32_t)(arow * 128 + (acs << 1) + 16));

    uint32_t uA[8];
    auto loadA = [&](int c) {
        const float* ap = Ab + (size_t)arow * F_ + c * 64 + acs;
        float4 v0 = *reinterpret_cast<const float4*>(ap);
        float4 v1 = *reinterpret_cast<const float4*>(ap + 4);
        float4 v2 = *reinterpret_cast<const float4*>(ap + 8);
        float4 v3 = *reinterpret_cast<const float4*>(ap + 12);
        uA[0] = pack2(v0.x, v0.y); uA[1] = pack2(v0.z, v0.w);
        uA[2] = pack2(v1.x, v1.y); uA[3] = pack2(v1.z, v1.w);
        uA[4] = pack2(v2.x, v2.y); uA[5] = pack2(v2.z, v2.w);
        uA[6] = pack2(v3.x, v3.y); uA[7] = pack2(v3.z, v3.w);
    };
    auto storeA = [&](int buf) {
        char* st = dsm + buf * STAGE + ST_A;
        *reinterpret_cast<uint4*>(st + a_st0) = make_uint4(uA[0], uA[1], uA[2], uA[3]);
        *reinterpret_cast<uint4*>(st + a_st1) = make_uint4(uA[4], uA[5], uA[6], uA[7]);
    };
    // B-tile loader via cp.async: 2048 16B lines / 256 threads = 8 each
    auto loadB = [&](int c, int buf) {
        const uint32_t stg = sbase + buf * STAGE + ST_B;
        const int k0 = c * 64;
        #pragma unroll
        for (int i = 0; i < 8; ++i) {
            int j = tid + (i << 8);             // 0..2047
            int row = j >> 3, seg = j & 7;
            uint32_t dst = stg + SWZ((uint32_t)(row * 128 + seg * 16));
            const __half* src = g_W1h + (size_t)row * F_ + k0 + seg * 8;
            cp_async16(dst, src);
        }
        CP_COMMIT();
    };

    // ---- prologue: fill both stages ----
    loadA(0); storeA(0); loadB(0, 0);
    loadA(1); storeA(1); loadB(1, 1);
    CP_WAIT1();
    __syncthreads();

    #pragma unroll 1
    for (int c = 0; c < 16; ++c) {
        const int buf = c & 1;
        const uint32_t aS = sbase + buf * STAGE + ST_A;
        const uint32_t bS = sbase + buf * STAGE + ST_B;

        if (c + 2 < 16) loadA(c + 2);   // issue globals before compute

        #pragma unroll
        for (int ks = 0; ks < 4; ++ks) {
            const uint32_t kb = (uint32_t)ks << 5;
            uint32_t ra[2][4];
            ldsm4(ra[0], aS + (a_base[0] ^ kb));
            ldsm4(ra[1], aS + (a_base[1] ^ kb));
            #pragma unroll
            for (int g = 0; g < 4; ++g) {
                uint32_t t4[4];
                ldsm4(t4, bS + (b_base[g] ^ kb));
                mma_f16(acc[0][2*g],   ra[0], &t4[0]);
                mma_f16(acc[0][2*g+1], ra[0], &t4[2]);
                mma_f16(acc[1][2*g],   ra[1], &t4[0]);
                mma_f16(acc[1][2*g+1], ra[1], &t4[2]);
            }
        }
        __syncthreads();                 // done reading stage[buf]
        if (c + 2 < 16) {
            storeA(buf);
            loadB(c + 2, buf);
            CP_WAIT1();
        } else {
            CP_WAIT0();
        }
        __syncthreads();
    }

    // ---------------- fused epilogue (1 batch elem) ----------------
    float* sD = (float*)dsm;                       // [64][SD_LD], aliases stages
    const float* b1s  = (const float*)(dsm + SM_B1);
    const float* a12s = (const float*)(dsm + SM_A12);
    const float* wa22 = (const float*)(dsm + SM_WA22);
    float* sz  = (float*)(dsm + SM_SZ);
    float* srs = (float*)(dsm + SM_SRS);
    float* srq = (float*)(dsm + SM_SRQ);
    float* sW  = (float*)(dsm + SM_SW);
    float* sab = (float*)(dsm + SM_AB);            // [0]=ab, [1]=bb
    float* sred = (float*)(dsm + SM_RED);

    {
        const int g8 = lane >> 2, tq = lane & 3;
        #pragma unroll
        for (int mt = 0; mt < 2; ++mt) {
            int row = (wm << 5) + (mt << 4) + g8;
            #pragma unroll
            for (int nt = 0; nt < 8; ++nt) {
                int col = (wn << 6) + (nt << 3) + (tq << 1);
                sD[row * SD_LD + col]           = acc[mt][nt][0] + b1s[col];
                sD[row * SD_LD + col + 1]       = acc[mt][nt][1] + b1s[col + 1];
                sD[(row + 8) * SD_LD + col]     = acc[mt][nt][2] + b1s[col];
                sD[(row + 8) * SD_LD + col + 1] = acc[mt][nt][3] + b1s[col + 1];
            }
        }
    }
    __syncthreads();

    // pass A: row stats (4 threads per row, 64 rows): BN sums + attn1 scores
    {
        const int r = tid >> 2, ph = tid & 3;
        float rs = 0.f, rq = 0.f, zz = 0.f;
        #pragma unroll 8
        for (int j = 0; j < 64; ++j) {
            int cc = ph + 4 * j;
            float v = sD[r * SD_LD + cc];
            rs += v; rq += v * v; zz += v * a12s[cc];
        }
        rs += __shfl_xor_sync(0xffffffffu, rs, 1); rs += __shfl_xor_sync(0xffffffffu, rs, 2);
        rq += __shfl_xor_sync(0xffffffffu, rq, 1); rq += __shfl_xor_sync(0xffffffffu, rq, 2);
        zz += __shfl_xor_sync(0xffffffffu, zz, 1); zz += __shfl_xor_sync(0xffffffffu, zz, 2);
        if (ph == 0) {
            srs[r] = rs; srq[r] = rq;
            float l = zz + g_t1[b];
            sz[r] = (l > 0.f) ? l : ALPHA_ * l;
        }
    }
    __syncthreads();

    // softmax weights (attn1) + per-b BN coefficients ab, bb
    if (tid < 64) {
        float mx = -1e30f;
        for (int j = 0; j < 64; ++j) mx = fmaxf(mx, sz[j]);
        float den = 0.f;
        for (int j = 0; j < 64; ++j) den += expf(sz[j] - mx);
        sW[tid] = expf(sz[tid] - mx) / den;
        if (tid == 0) {
            float s = 0.f, q = 0.f;
            for (int j = 0; j < 64; ++j) { s += srs[j]; q += srq[j]; }
            const float invb = 1.f / (float)(Nn * H1_);
            float mb = s * invb;
            float vb = q * invb - mb * mb;
            float ab = g1p[0] * rsqrtf(vb + BN_EPS_);
            sab[0] = ab;
            sab[1] = be1p[0] - ab * mb;
        }
    }
    __syncthreads();

    // pass B: layer-2 scores s2[n] = sum_h relu(ab*D+bb) * wa22[h] + c22
    {
        const int r = tid >> 2, ph = tid & 3;
        const float ab = sab[0], bb = sab[1];
        float z2 = 0.f;
        #pragma unroll 8
        for (int j = 0; j < 64; ++j) {
            int cc = ph + 4 * j;
            float v = fmaxf(ab * sD[r * SD_LD + cc] + bb, 0.f);
            z2 += v * wa22[cc];
        }
        z2 += __shfl_xor_sync(0xffffffffu, z2, 1);
        z2 += __shfl_xor_sync(0xffffffffu, z2, 2);
        if (ph == 0)
            g_s2[(size_t)b * Nn + r] = z2 + g_scalars[2];
    }

    // pass C: x1 (raw D x attn1 weights) + write v = relu(ab*D+bb) to global
    {
        const int h = tid;                       // 0..255
        const float ab = sab[0], bb = sab[1];
        float accx = 0.f;
        float* gout = g_v + (size_t)b * (Nn * H1_);
        #pragma unroll 8
        for (int n = 0; n < Nn; ++n) {
            float raw = sD[n * SD_LD + h];
            gout[n * H1_ + h] = fmaxf(ab * raw + bb, 0.f);
            accx += sW[n] * raw;
        }
        g_x1[(size_t)b * H1_ + h] = accx;
        float ts = blockSumB(accx, sred);
        if (tid == 0) atomicAdd(&g_scalars[3], ts);
        float tq2 = blockSumB(accx * accx, sred);
        if (tid == 0) atomicAdd(&g_scalars[4], tq2);
    }
}

// -------- K4: layer-2 softmax + weighted sum (single read of v) --------
__global__ void __launch_bounds__(256) k_attn2(const float* __restrict__ g1p,
                                               const float* __restrict__ be1p) {
    int b = blockIdx.x;
    int h = threadIdx.x;
    __shared__ float sS[Nn];
    __shared__ float sW[Nn];
    __shared__ float sred[32];

    const float invx = 1.f / (float)(B_ * H1_);
    float mxm = g_scalars[3] * invx;
    float vx  = g_scalars[4] * invx - mxm * mxm;
    float ax  = g1p[0] * rsqrtf(vx + BN_EPS_);
    float bx  = be1p[0] - ax * mxm;

    float u = fmaxf(ax * g_x1[b * H1_ + h] + bx, 0.f);
    float t2 = blockSumB(u * g_wa21h[h], sred) + g_scalars[1];

    if (h < Nn) {
        float s = t2 + g_s2[(size_t)b * Nn + h];
        sS[h] = (s > 0.f) ? s : ALPHA_ * s;
    }
    __syncthreads();
    float mx = -1e30f;
    for (int n = 0; n < Nn; ++n) mx = fmaxf(mx, sS[n]);
    float den = 0.f;
    for (int n = 0; n < Nn; ++n) den += expf(sS[n] - mx);
    if (h < Nn) sW[h] = expf(sS[h] - mx) / den;
    __syncthreads();

    const float* base = g_v + (size_t)b * (Nn * H1_);
    float y = 0.f;
    #pragma unroll 8
    for (int n = 0; n < Nn; ++n)
        y += sW[n] * base[n * H1_ + h];
    g_y[b * H1_ + h] = y;
}

// -------- K5: x2 = y @ W2^T + b2 --------
__global__ void __launch_bounds__(128) k_lin2(const float* __restrict__ b2) {
    int bb = blockIdx.x * 8;
    int h2 = threadIdx.x;
    __shared__ float sy[8 * H1_];
    __shared__ float sred[32];
    for (int i = h2; i < 8 * H1_; i += 128) sy[i] = g_y[(size_t)bb * H1_ + i];
    __syncthreads();
    float acc[8];
    #pragma unroll
    for (int i = 0; i < 8; ++i) acc[i] = 0.f;
    for (int k = 0; k < H1_; ++k) {
        float w = g_W2T[k * H2_ + h2];
        #pragma unroll
        for (int i = 0; i < 8; ++i) acc[i] += sy[i * H1_ + k] * w;
    }
    float b2v = b2[h2];
    float ls = 0.f, lq = 0.f;
    #pragma unroll
    for (int i = 0; i < 8; ++i) {
        float s = acc[i] + b2v;
        g_x2[(size_t)(bb + i) * H2_ + h2] = s;
        ls += s; lq += s * s;
    }
    float a = blockSumB(ls, sred);
    if (h2 == 0) atomicAdd(&g_scalars[5], a);
    float q = blockSumB(lq, sred);
    if (h2 == 0) atomicAdd(&g_scalars[6], q);
}

// -------- K6: logits = relu(bn(x2)) @ Wl^T + bl --------
__global__ void __launch_bounds__(128) k_final(const float* __restrict__ g2p,
                                               const float* __restrict__ be2p,
                                               const float* __restrict__ bl,
                                               float* __restrict__ out) {
    int bb = blockIdx.x * 8;
    int c = threadIdx.x;
    const float inv2 = 1.f / (float)(B_ * H2_);
    float m = g_scalars[5] * inv2;
    float v = g_scalars[6] * inv2 - m * m;
    float a2 = g2p[0] * rsqrtf(v + BN_EPS_);
    float s2 = be2p[0] - a2 * m;
    __shared__ float sx[8 * H2_];
    #pragma unroll
    for (int i = 0; i < 8; ++i) {
        float t = a2 * g_x2[(size_t)(bb + i) * H2_ + c] + s2;
        sx[i * H2_ + c] = fmaxf(t, 0.f);
    }
    __syncthreads();
    float acc[8];
    #pragma unroll
    for (int i = 0; i < 8; ++i) acc[i] = 0.f;
    for (int k = 0; k < H2_; ++k) {
        float w = g_WlT[k * NC_ + c];
        #pragma unroll
        for (int i = 0; i < 8; ++i) acc[i] += sx[i * H2_ + k] * w;
    }
    float blc = bl[c];
    #pragma unroll
    for (int i = 0; i < 8; ++i) out[(size_t)(bb + i) * NC_ + c] = acc[i] + blc;
}

extern "C" void kernel_launch(void* const* d_in, const int* in_sizes, int n_in,
                              void* d_out, int out_size) {
    const float* x   = (const float*)d_in[0];
    const float* nb  = (const float*)d_in[1];
    const float* W1  = (const float*)d_in[2];
    const float* b1  = (const float*)d_in[3];
    const float* a11 = (const float*)d_in[4];
    const float* a12 = (const float*)d_in[5];
    const float* g1  = (const float*)d_in[6];
    const float* be1 = (const float*)d_in[7];
    const float* W2  = (const float*)d_in[8];
    const float* b2  = (const float*)d_in[9];
    const float* a21 = (const float*)d_in[10];
    const float* a22 = (const float*)d_in[11];
    const float* g2  = (const float*)d_in[12];
    const float* be2 = (const float*)d_in[13];
    const float* Wl  = (const float*)d_in[14];
    const float* bl  = (const float*)d_in[15];
    float* out = (float*)d_out;

    static int smem_set = 0;
    if (!smem_set) {
        cudaFuncSetAttribute(k_gemm, cudaFuncAttributeMaxDynamicSharedMemorySize, GEMM_SMEM);
        smem_set = 1;
    }

    k_pre<<<32, 256>>>(W1, b1, a11, W2, b2, a21, a22, Wl);
    k_t1<<<B_, 256>>>(x);
    k_gemm<<<B_, 256, GEMM_SMEM>>>(nb, b1, a12, g1, be1);
    k_attn2<<<B_, 256>>>(g1, be1);
    k_lin2<<<B_ / 8, 128>>>(b2);
    k_final<<<B_ / 8, 128>>>(g2, be2, bl, out);
}